// round 1
// baseline (speedup 1.0000x reference)
#include <cuda_runtime.h>

#define KNN 10
#define NPTS 2048
#define NB 8
#define LRELU(h) ((h) >= 0.f ? (h) : 0.2f * (h))

// ---------------- scratch (device globals; no runtime allocation) ----------------
__device__ float g_xcat[NB * NPTS * 512];          // concat of out1..out4 (offsets 0,64,128,256)
__device__ float g_dot[NB * NPTS * NPTS];          // gram matrix per batch
__device__ int   g_idx[NB * NPTS * KNN];           // knn indices
__device__ float g_dif[NB * NPTS * KNN * 128];     // edge diff features (max C=128)
__device__ float g_gg1[NB * NPTS * KNN * 256];     // diff GEMM output (max O=256)
__device__ float g_bse[NB * NPTS * 256];           // base GEMM output
__device__ float g_hh[NB * NPTS * 1024];           // W5 output
__device__ float g_pool[NB * 1024];                // pooled features

// ---------------- generic NT GEMM: C[m][n] = sum_k A[m][k] * B[n][k] -------------
// A: M x K row-major (lda), B: N x K row-major (ldb), C: M x N (ldc). Batched via z.
// M, N must be multiples of 64 (true for all our shapes). K guarded.
#define TM 64
#define TN 64
#define TK 16
__global__ void gemm_nt(const float* __restrict__ A, const float* __restrict__ Bm,
                        float* __restrict__ Cm, int M, int Nn, int Kd,
                        int lda, int ldb, int ldc,
                        long long sA, long long sB, long long sC)
{
    __shared__ float As[TK][TM];
    __shared__ float Bs[TK][TN];
    A  += (long long)blockIdx.z * sA;
    Bm += (long long)blockIdx.z * sB;
    Cm += (long long)blockIdx.z * sC;
    const int m0 = blockIdx.x * TM, n0 = blockIdx.y * TN;
    const int tid = threadIdx.x;           // 256 threads
    const int tx = tid & 15, ty = tid >> 4;

    float acc[4][4];
#pragma unroll
    for (int i = 0; i < 4; i++)
#pragma unroll
        for (int j = 0; j < 4; j++) acc[i][j] = 0.f;

    for (int k0 = 0; k0 < Kd; k0 += TK) {
#pragma unroll
        for (int i = 0; i < 4; i++) {
            int e = tid + i * 256;
            int r = e >> 4, kk = e & 15;
            int kidx = k0 + kk;
            As[kk][r] = (kidx < Kd) ? A[(long long)(m0 + r) * lda + kidx] : 0.f;
            Bs[kk][r] = (kidx < Kd) ? Bm[(long long)(n0 + r) * ldb + kidx] : 0.f;
        }
        __syncthreads();
#pragma unroll
        for (int kk = 0; kk < TK; ++kk) {
            float av[4], bv[4];
#pragma unroll
            for (int i = 0; i < 4; i++) av[i] = As[kk][ty * 4 + i];
#pragma unroll
            for (int j = 0; j < 4; j++) bv[j] = Bs[kk][tx * 4 + j];
#pragma unroll
            for (int i = 0; i < 4; i++)
#pragma unroll
                for (int j = 0; j < 4; j++)
                    acc[i][j] = fmaf(av[i], bv[j], acc[i][j]);
        }
        __syncthreads();
    }
#pragma unroll
    for (int i = 0; i < 4; i++)
#pragma unroll
        for (int j = 0; j < 4; j++)
            Cm[(long long)(m0 + ty * 4 + i) * ldc + (n0 + tx * 4 + j)] = acc[i][j];
}

// ---------------- knn selection from gram matrix ---------------------------------
// ranking key: d(i,j) = |x_j|^2 - 2 x_i.x_j  (|x_i|^2 constant per query i).
// Dot symmetric => read Dot[j][i] (coalesced over i). Stable ties: strict-less insert.
__global__ void knn_select(const float* __restrict__ dotm, int* __restrict__ idx)
{
    int b = blockIdx.y;
    int i = blockIdx.x * blockDim.x + threadIdx.x;
    const float* D = dotm + (long long)b * NPTS * NPTS;

    float bd[KNN];
    int bi[KNN];
#pragma unroll
    for (int q = 0; q < KNN; q++) { bd[q] = 3.4e38f; bi[q] = -1; }
    float worst = 3.4e38f;

    for (int j = 0; j < NPTS; j++) {
        const float* row = D + (long long)j * NPTS;
        float nj = __ldg(row + j);
        float d = fmaf(-2.f, __ldg(row + i), nj);
        if (j != i && d < worst) {
            int p = KNN - 1;
            while (p > 0 && bd[p - 1] > d) {
                bd[p] = bd[p - 1]; bi[p] = bi[p - 1]; p--;
            }
            bd[p] = d; bi[p] = j;
            worst = bd[KNN - 1];
        }
    }
    int* o = idx + ((long long)b * NPTS + i) * KNN;
#pragma unroll
    for (int q = 0; q < KNN; q++) o[q] = bi[q];
}

// ---------------- build diff features: dif[bn,k,c] = x_j[c] - x_i[c] -------------
__global__ void gather_diff(const float* __restrict__ feat, int lda, int C,
                            const int* __restrict__ idx, float* __restrict__ dif,
                            int total)
{
    int g = blockIdx.x * blockDim.x + threadIdx.x;
    if (g >= total) return;
    int c = g % C;
    int t = g / C;          // = bn*KNN + k
    int bn = t / KNN;
    int j = idx[t];
    int b = bn >> 11;       // /NPTS
    int rj = (b << 11) + j;
    dif[g] = feat[(long long)rj * lda + c] - feat[(long long)bn * lda + c];
}

// ---------------- combine: max over k, affine, lrelu, write into xcat slice ------
__global__ void combine_max(const float* __restrict__ gd, const float* __restrict__ base,
                            const float* __restrict__ s, const float* __restrict__ t,
                            float* __restrict__ outx, int O)
{
    int g = blockIdx.x * blockDim.x + threadIdx.x;  // bn*O + o
    int o = g % O;
    int bn = g / O;
    float m = -3.4e38f;
#pragma unroll
    for (int k = 0; k < KNN; k++)
        m = fmaxf(m, gd[((long long)bn * KNN + k) * O + o]);
    float h = (m + base[g]) * s[o] + t[o];
    outx[(long long)bn * 512 + o] = LRELU(h);
}

// ---------------- global max pool over N + affine + lrelu ------------------------
__global__ void maxpool(const float* __restrict__ H, const float* __restrict__ s5,
                        const float* __restrict__ t5, float* __restrict__ pooled)
{
    int b = blockIdx.y;
    int o = blockIdx.x * blockDim.x + threadIdx.x;   // 0..1023
    const float* p = H + (long long)b * NPTS * 1024 + o;
    float m0 = -3.4e38f, m1 = -3.4e38f, m2 = -3.4e38f, m3 = -3.4e38f;
    for (int n = 0; n < NPTS; n += 4) {
        m0 = fmaxf(m0, p[(long long)(n + 0) * 1024]);
        m1 = fmaxf(m1, p[(long long)(n + 1) * 1024]);
        m2 = fmaxf(m2, p[(long long)(n + 2) * 1024]);
        m3 = fmaxf(m3, p[(long long)(n + 3) * 1024]);
    }
    float m = fmaxf(fmaxf(m0, m1), fmaxf(m2, m3));
    float h = m * s5[o] + t5[o];
    pooled[b * 1024 + o] = LRELU(h);
}

// ---------------- final 3 FC layers, fused; one block per batch -------------------
__global__ void final_fc(const float* __restrict__ pooled,
                         const float* __restrict__ Wf1, const float* __restrict__ sf1,
                         const float* __restrict__ tf1,
                         const float* __restrict__ Wf2, const float* __restrict__ bf2,
                         const float* __restrict__ sf2, const float* __restrict__ tf2,
                         const float* __restrict__ Wf3, const float* __restrict__ bf3,
                         float* __restrict__ out)
{
    __shared__ float sx[1024];
    __shared__ float h1[512];
    __shared__ float h2[256];
    int b = blockIdx.x, tid = threadIdx.x;   // 512 threads
    sx[tid] = pooled[b * 1024 + tid];
    sx[tid + 512] = pooled[b * 1024 + tid + 512];
    __syncthreads();
    {
        const float* w = Wf1 + (long long)tid * 1024;
        float a0 = 0.f, a1 = 0.f, a2 = 0.f, a3 = 0.f;
        for (int c = 0; c < 1024; c += 4) {
            a0 = fmaf(w[c + 0], sx[c + 0], a0);
            a1 = fmaf(w[c + 1], sx[c + 1], a1);
            a2 = fmaf(w[c + 2], sx[c + 2], a2);
            a3 = fmaf(w[c + 3], sx[c + 3], a3);
        }
        float h = ((a0 + a1) + (a2 + a3)) * sf1[tid] + tf1[tid];
        h1[tid] = LRELU(h);
    }
    __syncthreads();
    if (tid < 256) {
        const float* w = Wf2 + (long long)tid * 512;
        float a0 = 0.f, a1 = 0.f, a2 = 0.f, a3 = 0.f;
        for (int c = 0; c < 512; c += 4) {
            a0 = fmaf(w[c + 0], h1[c + 0], a0);
            a1 = fmaf(w[c + 1], h1[c + 1], a1);
            a2 = fmaf(w[c + 2], h1[c + 2], a2);
            a3 = fmaf(w[c + 3], h1[c + 3], a3);
        }
        float h = (((a0 + a1) + (a2 + a3)) + bf2[tid]) * sf2[tid] + tf2[tid];
        h2[tid] = LRELU(h);
    }
    __syncthreads();
    if (tid < 3) {
        const float* w = Wf3 + (long long)tid * 256;
        float a = 0.f;
        for (int c = 0; c < 256; c++) a = fmaf(w[c], h2[c], a);
        out[b * 3 + tid] = a + bf3[tid];
    }
}

// ------------------------------- host side ---------------------------------------
extern "C" void kernel_launch(void* const* d_in, const int* in_sizes, int n_in,
                              void* d_out, int out_size)
{
    const float* points = (const float*)d_in[0];
    const float* W1 = (const float*)d_in[1];  const float* s1 = (const float*)d_in[2];  const float* t1 = (const float*)d_in[3];
    const float* W2 = (const float*)d_in[4];  const float* s2 = (const float*)d_in[5];  const float* t2 = (const float*)d_in[6];
    const float* W3 = (const float*)d_in[7];  const float* s3 = (const float*)d_in[8];  const float* t3 = (const float*)d_in[9];
    const float* W4 = (const float*)d_in[10]; const float* s4 = (const float*)d_in[11]; const float* t4 = (const float*)d_in[12];
    const float* W5 = (const float*)d_in[13]; const float* s5 = (const float*)d_in[14]; const float* t5 = (const float*)d_in[15];
    const float* Wf1 = (const float*)d_in[16]; const float* sf1 = (const float*)d_in[17]; const float* tf1 = (const float*)d_in[18];
    const float* Wf2 = (const float*)d_in[19]; const float* bf2 = (const float*)d_in[20];
    const float* sf2 = (const float*)d_in[21]; const float* tf2 = (const float*)d_in[22];
    const float* Wf3 = (const float*)d_in[23]; const float* bf3 = (const float*)d_in[24];

    float *xcat, *dotm, *dif, *gd, *base, *hh, *pool;
    int* idx;
    cudaGetSymbolAddress((void**)&xcat, g_xcat);
    cudaGetSymbolAddress((void**)&dotm, g_dot);
    cudaGetSymbolAddress((void**)&idx,  g_idx);
    cudaGetSymbolAddress((void**)&dif,  g_dif);
    cudaGetSymbolAddress((void**)&gd,   g_gg1);
    cudaGetSymbolAddress((void**)&base, g_bse);
    cudaGetSymbolAddress((void**)&hh,   g_hh);
    cudaGetSymbolAddress((void**)&pool, g_pool);

    const int BN = NB * NPTS;          // 16384
    const int BNK = BN * KNN;          // 163840

    auto edge = [&](const float* feat, int lda, int C, int O,
                    const float* W, const float* s, const float* t, int coffOut) {
        // 1) gram per batch: Dot = X X^T
        gemm_nt<<<dim3(NPTS / 64, NPTS / 64, NB), 256>>>(
            feat, feat, dotm, NPTS, NPTS, C, lda, lda, NPTS,
            (long long)NPTS * lda, (long long)NPTS * lda, (long long)NPTS * NPTS);
        // 2) knn
        knn_select<<<dim3(NPTS / 256, NB), 256>>>(dotm, idx);
        // 3) diff features
        int total = BNK * C;
        gather_diff<<<(total + 255) / 256, 256>>>(feat, lda, C, idx, dif, total);
        // 4) diff GEMM: (BNK x C) @ (C x O)   [first C cols of W]
        gemm_nt<<<dim3(BNK / 64, O / 64, 1), 256>>>(
            dif, W, gd, BNK, O, C, C, 2 * C, O, 0, 0, 0);
        // 5) base GEMM: (BN x C) @ (C x O)    [last C cols of W]
        gemm_nt<<<dim3(BN / 64, O / 64, 1), 256>>>(
            feat, W + C, base, BN, O, C, lda, 2 * C, O, 0, 0, 0);
        // 6) combine: max over k, affine+lrelu, write into xcat slice
        combine_max<<<(BN * O) / 256, 256>>>(gd, base, s, t, xcat + coffOut, O);
    };

    edge(points,      3,   3,  64, W1, s1, t1, 0);
    edge(xcat + 0,   512, 64,  64, W2, s2, t2, 64);
    edge(xcat + 64,  512, 64, 128, W3, s3, t3, 128);
    edge(xcat + 128, 512, 128, 256, W4, s4, t4, 256);

    // point MLP: (16384 x 512) @ (512 x 1024)
    gemm_nt<<<dim3(BN / 64, 1024 / 64, 1), 256>>>(
        xcat, W5, hh, BN, 1024, 512, 512, 512, 1024, 0, 0, 0);
    // global max pool + affine + lrelu  (s5>0 so affine/lrelu commute with max)
    maxpool<<<dim3(1024 / 256, NB), 256>>>(hh, s5, t5, pool);
    // final FCs
    final_fc<<<NB, 512>>>(pool, Wf1, sf1, tf1, Wf2, bf2, sf2, tf2, Wf3, bf3,
                          (float*)d_out);
}

// round 2
// speedup vs baseline: 4.1599x; 4.1599x over previous
#include <cuda_runtime.h>

#define KNN 10
#define NPTS 2048
#define NB 8
#define BN_TOT (NB * NPTS)
#define LRELU(h) ((h) >= 0.f ? (h) : 0.2f * (h))

// ---------------- scratch (device globals; no runtime allocation) ----------------
__device__ float g_xcat[BN_TOT * 512];        // concat of out1..out4 (offsets 0,64,128,256)
__device__ float g_dot[NB * NPTS * NPTS];     // gram matrix per batch (134MB)
__device__ float g_nrm[BN_TOT];               // squared norms (gram diagonal)
__device__ int   g_idx[BN_TOT * KNN];         // knn indices
__device__ float g_yd[BN_TOT * 256];          // X @ Wdiff^T
__device__ float g_yb[BN_TOT * 256];          // X @ Wbase^T
__device__ float g_hh[BN_TOT * 1024];         // W5 output
__device__ float g_pool[NB * 1024];           // pooled features
__device__ float g_pts[BN_TOT * 4];           // points padded to C=4
__device__ float g_w1d[64 * 4];               // W1 diff half padded
__device__ float g_w1b[64 * 4];               // W1 base half padded

// ================= 128x128 SIMT GEMM, 8x8 micro-tile, NT form ====================
// C[m][n] = sum_k A[m][k]*B[n][k].  M % 128 == 0.  N % 64 == 0 (col-guarded).
// K % 4 == 0 (float4-granular guard). Batched via z strides.
#define BM 128
#define BNT 128
#define BK 16
__global__ __launch_bounds__(256) void gemm128(
    const float* __restrict__ A, const float* __restrict__ B, float* __restrict__ C,
    int M, int N, int K, int lda, int ldb, int ldc,
    long long sA, long long sB, long long sC)
{
    __shared__ float As[BK][BM + 4];
    __shared__ float Bs[BK][BNT + 4];
    A += (long long)blockIdx.z * sA;
    B += (long long)blockIdx.z * sB;
    C += (long long)blockIdx.z * sC;
    const int m0 = blockIdx.x * BM, n0 = blockIdx.y * BNT;
    const int tid = threadIdx.x;
    const int tx = tid & 15, ty = tid >> 4;

    float acc[8][8];
#pragma unroll
    for (int i = 0; i < 8; i++)
#pragma unroll
        for (int j = 0; j < 8; j++) acc[i][j] = 0.f;

    for (int k0 = 0; k0 < K; k0 += BK) {
#pragma unroll
        for (int h = 0; h < 2; h++) {
            int f = tid + h * 256;
            int row = f >> 2;
            int kq = (f & 3) * 4;
            float4 va = make_float4(0.f, 0.f, 0.f, 0.f);
            if (k0 + kq < K)
                va = *(const float4*)(A + (long long)(m0 + row) * lda + k0 + kq);
            As[kq + 0][row] = va.x; As[kq + 1][row] = va.y;
            As[kq + 2][row] = va.z; As[kq + 3][row] = va.w;
            float4 vb = make_float4(0.f, 0.f, 0.f, 0.f);
            if (k0 + kq < K && n0 + row < N)
                vb = *(const float4*)(B + (long long)(n0 + row) * ldb + k0 + kq);
            Bs[kq + 0][row] = vb.x; Bs[kq + 1][row] = vb.y;
            Bs[kq + 2][row] = vb.z; Bs[kq + 3][row] = vb.w;
        }
        __syncthreads();
#pragma unroll
        for (int kk = 0; kk < BK; kk++) {
            float a[8], b[8];
            *(float4*)(&a[0]) = *(const float4*)(&As[kk][ty * 4]);
            *(float4*)(&a[4]) = *(const float4*)(&As[kk][ty * 4 + 64]);
            *(float4*)(&b[0]) = *(const float4*)(&Bs[kk][tx * 4]);
            *(float4*)(&b[4]) = *(const float4*)(&Bs[kk][tx * 4 + 64]);
#pragma unroll
            for (int i = 0; i < 8; i++)
#pragma unroll
                for (int j = 0; j < 8; j++)
                    acc[i][j] = fmaf(a[i], b[j], acc[i][j]);
        }
        __syncthreads();
    }
#pragma unroll
    for (int ih = 0; ih < 2; ih++)
#pragma unroll
        for (int i2 = 0; i2 < 4; i2++) {
            int i = ih * 4 + i2;
            long long r = m0 + ty * 4 + ih * 64 + i2;
#pragma unroll
            for (int jh = 0; jh < 2; jh++) {
                int cb = n0 + tx * 4 + jh * 64;
                if (cb < N) {
                    float4 v;
                    v.x = acc[i][jh * 4 + 0]; v.y = acc[i][jh * 4 + 1];
                    v.z = acc[i][jh * 4 + 2]; v.w = acc[i][jh * 4 + 3];
                    *(float4*)(C + r * ldc + cb) = v;
                }
            }
        }
}

// ---------------- extract gram diagonal -> squared norms -------------------------
__global__ void diag_norms(const float* __restrict__ dotm, float* __restrict__ nrm)
{
    int g = blockIdx.x * blockDim.x + threadIdx.x;   // 0..BN_TOT
    int b = g >> 11, i = g & 2047;
    nrm[g] = dotm[((long long)b * NPTS + i) * NPTS + i];
}

// ---------------- knn: warp per query, register top-10, shuffle merge ------------
// key: d(i,j) = |x_j|^2 - 2 x_i.x_j  (|x_i|^2 constant per i). Ties: lower j wins.
__global__ void knn_warp(const float* __restrict__ dotm, const float* __restrict__ nrm,
                         int* __restrict__ idx)
{
    int warp = (blockIdx.x * blockDim.x + threadIdx.x) >> 5;
    int lane = threadIdx.x & 31;
    int b = warp >> 11;           // / NPTS
    int i = warp & 2047;
    const float* row = dotm + ((long long)b * NPTS + i) * NPTS;   // symmetric: row i
    const float* nr = nrm + b * NPTS;

    float bd[KNN];
    int bi[KNN];
#pragma unroll
    for (int q = 0; q < KNN; q++) { bd[q] = 3.4e38f; bi[q] = 0x7fffffff; }

    for (int j = lane; j < NPTS; j += 32) {
        if (j == i) continue;
        float d = fmaf(-2.f, __ldg(row + j), __ldg(nr + j));
        if (d < bd[KNN - 1]) {              // strict: equal-d keeps earlier (smaller) j
            bd[KNN - 1] = d; bi[KNN - 1] = j;
#pragma unroll
            for (int p = KNN - 1; p > 0; p--) {
                if (bd[p] < bd[p - 1]) {    // strict: stable for ties
                    float td = bd[p]; bd[p] = bd[p - 1]; bd[p - 1] = td;
                    int tj = bi[p]; bi[p] = bi[p - 1]; bi[p - 1] = tj;
                }
            }
        }
    }

    int* o = idx + (long long)warp * KNN;
    for (int q = 0; q < KNN; q++) {
        float d0 = bd[0];
        int j0 = bi[0];
#pragma unroll
        for (int off = 16; off > 0; off >>= 1) {
            float od = __shfl_xor_sync(0xffffffffu, d0, off);
            int oj = __shfl_xor_sync(0xffffffffu, j0, off);
            if (od < d0 || (od == d0 && oj < j0)) { d0 = od; j0 = oj; }
        }
        if (lane == 0) o[q] = j0;
        if (bi[0] == j0) {                  // this lane supplied the winner: pop head
#pragma unroll
            for (int p = 0; p < KNN - 1; p++) { bd[p] = bd[p + 1]; bi[p] = bi[p + 1]; }
            bd[KNN - 1] = 3.4e38f; bi[KNN - 1] = 0x7fffffff;
        }
    }
}

// ---------------- combine: max_k(yd[j_k]) - yd[i] + yb[i], affine, lrelu ---------
__global__ void combine2(const float* __restrict__ yd, const float* __restrict__ yb,
                         const int* __restrict__ idx, const float* __restrict__ s,
                         const float* __restrict__ t, float* __restrict__ outx, int O)
{
    int g = blockIdx.x * blockDim.x + threadIdx.x;   // bn*O + o
    int bn = g / O;
    int o = g - bn * O;
    const int* ip = idx + (long long)bn * KNN;
    int base = bn & ~2047;                           // batch row base
    float m = -3.4e38f;
#pragma unroll
    for (int k = 0; k < KNN; k++) {
        int j = ip[k];
        m = fmaxf(m, yd[(long long)(base + j) * O + o]);
    }
    float h = (m - yd[g] + yb[g]) * s[o] + t[o];
    outx[(long long)bn * 512 + o] = LRELU(h);
}

// ---------------- input padding helpers -------------------------------------------
__global__ void pad_pts(const float* __restrict__ p, float* __restrict__ pp)
{
    int g = blockIdx.x * blockDim.x + threadIdx.x;   // BN_TOT
    pp[g * 4 + 0] = p[g * 3 + 0];
    pp[g * 4 + 1] = p[g * 3 + 1];
    pp[g * 4 + 2] = p[g * 3 + 2];
    pp[g * 4 + 3] = 0.f;
}
__global__ void pad_w1(const float* __restrict__ W1, float* __restrict__ wd,
                       float* __restrict__ wb)
{
    int o = threadIdx.x;   // 64
#pragma unroll
    for (int c = 0; c < 3; c++) {
        wd[o * 4 + c] = W1[o * 6 + c];
        wb[o * 4 + c] = W1[o * 6 + 3 + c];
    }
    wd[o * 4 + 3] = 0.f;
    wb[o * 4 + 3] = 0.f;
}

// ---------------- global max pool over N + affine + lrelu ------------------------
__global__ void maxpool(const float* __restrict__ H, const float* __restrict__ s5,
                        const float* __restrict__ t5, float* __restrict__ pooled)
{
    int b = blockIdx.y;
    int o = blockIdx.x * blockDim.x + threadIdx.x;   // 0..1023
    const float* p = H + (long long)b * NPTS * 1024 + o;
    float m0 = -3.4e38f, m1 = -3.4e38f, m2 = -3.4e38f, m3 = -3.4e38f;
    for (int n = 0; n < NPTS; n += 4) {
        m0 = fmaxf(m0, p[(long long)(n + 0) * 1024]);
        m1 = fmaxf(m1, p[(long long)(n + 1) * 1024]);
        m2 = fmaxf(m2, p[(long long)(n + 2) * 1024]);
        m3 = fmaxf(m3, p[(long long)(n + 3) * 1024]);
    }
    float m = fmaxf(fmaxf(m0, m1), fmaxf(m2, m3));
    float h = m * s5[o] + t5[o];
    pooled[b * 1024 + o] = LRELU(h);
}

// ---------------- final 3 FC layers, fused; one block per batch -------------------
__global__ void final_fc(const float* __restrict__ pooled,
                         const float* __restrict__ Wf1, const float* __restrict__ sf1,
                         const float* __restrict__ tf1,
                         const float* __restrict__ Wf2, const float* __restrict__ bf2,
                         const float* __restrict__ sf2, const float* __restrict__ tf2,
                         const float* __restrict__ Wf3, const float* __restrict__ bf3,
                         float* __restrict__ out)
{
    __shared__ float sx[1024];
    __shared__ float h1[512];
    __shared__ float h2[256];
    int b = blockIdx.x, tid = threadIdx.x;   // 512 threads
    sx[tid] = pooled[b * 1024 + tid];
    sx[tid + 512] = pooled[b * 1024 + tid + 512];
    __syncthreads();
    {
        const float* w = Wf1 + (long long)tid * 1024;
        float a0 = 0.f, a1 = 0.f, a2 = 0.f, a3 = 0.f;
        for (int c = 0; c < 1024; c += 4) {
            a0 = fmaf(w[c + 0], sx[c + 0], a0);
            a1 = fmaf(w[c + 1], sx[c + 1], a1);
            a2 = fmaf(w[c + 2], sx[c + 2], a2);
            a3 = fmaf(w[c + 3], sx[c + 3], a3);
        }
        float h = ((a0 + a1) + (a2 + a3)) * sf1[tid] + tf1[tid];
        h1[tid] = LRELU(h);
    }
    __syncthreads();
    if (tid < 256) {
        const float* w = Wf2 + (long long)tid * 512;
        float a0 = 0.f, a1 = 0.f, a2 = 0.f, a3 = 0.f;
        for (int c = 0; c < 512; c += 4) {
            a0 = fmaf(w[c + 0], h1[c + 0], a0);
            a1 = fmaf(w[c + 1], h1[c + 1], a1);
            a2 = fmaf(w[c + 2], h1[c + 2], a2);
            a3 = fmaf(w[c + 3], h1[c + 3], a3);
        }
        float h = (((a0 + a1) + (a2 + a3)) + bf2[tid]) * sf2[tid] + tf2[tid];
        h2[tid] = LRELU(h);
    }
    __syncthreads();
    if (tid < 3) {
        const float* w = Wf3 + (long long)tid * 256;
        float a = 0.f;
        for (int c = 0; c < 256; c++) a = fmaf(w[c], h2[c], a);
        out[b * 3 + tid] = a + bf3[tid];
    }
}

// ------------------------------- host side ---------------------------------------
extern "C" void kernel_launch(void* const* d_in, const int* in_sizes, int n_in,
                              void* d_out, int out_size)
{
    const float* points = (const float*)d_in[0];
    const float* W1 = (const float*)d_in[1];  const float* s1 = (const float*)d_in[2];  const float* t1 = (const float*)d_in[3];
    const float* W2 = (const float*)d_in[4];  const float* s2 = (const float*)d_in[5];  const float* t2 = (const float*)d_in[6];
    const float* W3 = (const float*)d_in[7];  const float* s3 = (const float*)d_in[8];  const float* t3 = (const float*)d_in[9];
    const float* W4 = (const float*)d_in[10]; const float* s4 = (const float*)d_in[11]; const float* t4 = (const float*)d_in[12];
    const float* W5 = (const float*)d_in[13]; const float* s5 = (const float*)d_in[14]; const float* t5 = (const float*)d_in[15];
    const float* Wf1 = (const float*)d_in[16]; const float* sf1 = (const float*)d_in[17]; const float* tf1 = (const float*)d_in[18];
    const float* Wf2 = (const float*)d_in[19]; const float* bf2 = (const float*)d_in[20];
    const float* sf2 = (const float*)d_in[21]; const float* tf2 = (const float*)d_in[22];
    const float* Wf3 = (const float*)d_in[23]; const float* bf3 = (const float*)d_in[24];

    float *xcat, *dotm, *nrm, *yd, *yb, *hh, *pool, *pts, *w1d, *w1b;
    int* idx;
    cudaGetSymbolAddress((void**)&xcat, g_xcat);
    cudaGetSymbolAddress((void**)&dotm, g_dot);
    cudaGetSymbolAddress((void**)&nrm,  g_nrm);
    cudaGetSymbolAddress((void**)&idx,  g_idx);
    cudaGetSymbolAddress((void**)&yd,   g_yd);
    cudaGetSymbolAddress((void**)&yb,   g_yb);
    cudaGetSymbolAddress((void**)&hh,   g_hh);
    cudaGetSymbolAddress((void**)&pool, g_pool);
    cudaGetSymbolAddress((void**)&pts,  g_pts);
    cudaGetSymbolAddress((void**)&w1d,  g_w1d);
    cudaGetSymbolAddress((void**)&w1b,  g_w1b);

    const int BN = BN_TOT;   // 16384

    pad_pts<<<BN / 256, 256>>>(points, pts);
    pad_w1<<<1, 64>>>(W1, w1d, w1b);

    // edge layer: feat (BN x C, lda), Wd/Wb (O x C, ldb), output -> xcat slice
    auto edge = [&](const float* feat, int lda, int C, int O,
                    const float* Wd, const float* Wb, int ldb,
                    const float* s, const float* t, int coff) {
        // gram per batch: Dot = X X^T
        gemm128<<<dim3(NPTS / 128, NPTS / 128, NB), 256>>>(
            feat, feat, dotm, NPTS, NPTS, C, lda, lda, NPTS,
            (long long)NPTS * lda, (long long)NPTS * lda, (long long)NPTS * NPTS);
        diag_norms<<<BN / 256, 256>>>(dotm, nrm);
        knn_warp<<<(BN * 32) / 256, 256>>>(dotm, nrm, idx);
        // yd = X @ Wd^T, yb = X @ Wb^T  (edge-conv linearity: no BNK GEMM needed)
        gemm128<<<dim3(BN / 128, (O + 127) / 128, 1), 256>>>(
            feat, Wd, yd, BN, O, C, lda, ldb, O, 0, 0, 0);
        gemm128<<<dim3(BN / 128, (O + 127) / 128, 1), 256>>>(
            feat, Wb, yb, BN, O, C, lda, ldb, O, 0, 0, 0);
        combine2<<<(BN * O) / 256, 256>>>(yd, yb, idx, s, t, xcat + coff, O);
    };

    edge(pts,        4,   4,  64, w1d,      w1b,      4,   s1, t1, 0);
    edge(xcat + 0,   512, 64,  64, W2,       W2 + 64,  128, s2, t2, 64);
    edge(xcat + 64,  512, 64, 128, W3,       W3 + 64,  128, s3, t3, 128);
    edge(xcat + 128, 512, 128, 256, W4,      W4 + 128, 256, s4, t4, 256);

    // point MLP: (16384 x 512) @ (512 x 1024)^T
    gemm128<<<dim3(BN / 128, 1024 / 128, 1), 256>>>(
        xcat, W5, hh, BN, 1024, 512, 512, 512, 1024, 0, 0, 0);
    // global max pool + affine + lrelu  (s5>0: affine/lrelu commute with max)
    maxpool<<<dim3(1024 / 256, NB), 256>>>(hh, s5, t5, pool);
    final_fc<<<NB, 512>>>(pool, Wf1, sf1, tf1, Wf2, bf2, sf2, tf2, Wf3, bf3,
                          (float*)d_out);
}

// round 3
// speedup vs baseline: 4.3866x; 1.0545x over previous
#include <cuda_runtime.h>

#define KNN 10
#define NPTS 2048
#define NB 8
#define BN_TOT (NB * NPTS)
#define LRELU(h) ((h) >= 0.f ? (h) : 0.2f * (h))

// ---------------- scratch (device globals; no runtime allocation) ----------------
__device__ float g_xcat[BN_TOT * 512];        // concat of out1..out4 (offsets 0,64,128,256)
__device__ float g_dot[NB * NPTS * NPTS];     // gram matrix per batch (134MB)
__device__ float g_nrm[BN_TOT];               // squared norms (gram diagonal)
__device__ int   g_idx[BN_TOT * KNN];         // knn indices
__device__ float g_yd[BN_TOT * 256];          // X @ Wdiff^T
__device__ float g_yb[BN_TOT * 256];          // X @ Wbase^T
__device__ float g_hh[BN_TOT * 1024];         // W5 output
__device__ float g_pool[NB * 1024];           // pooled features
__device__ float g_pts[BN_TOT * 4];           // points padded to C=4
__device__ float g_w1d[64 * 4];               // W1 diff half padded
__device__ float g_w1b[64 * 4];               // W1 base half padded

// ---------------- packed f32x2 helpers --------------------------------------------
__device__ __forceinline__ void ffma2(unsigned long long& d,
                                      unsigned long long a, unsigned long long b)
{
    asm("fma.rn.f32x2 %0, %1, %2, %0;" : "+l"(d) : "l"(a), "l"(b));
}
__device__ __forceinline__ unsigned long long dup2(float a)
{
    unsigned long long p;
    asm("mov.b64 %0, {%1, %1};" : "=l"(p) : "f"(a));
    return p;
}
__device__ __forceinline__ float2 unpk(unsigned long long p)
{
    float2 f;
    asm("mov.b64 {%0, %1}, %2;" : "=f"(f.x), "=f"(f.y) : "l"(p));
    return f;
}

// ================= 128x128 GEMM, 8x8 micro-tile, FFMA2 math, NT form =============
// C[m][n] = sum_k A[m][k]*B[n][k].  M % 128 == 0.  N col-guarded. K % 4 == 0.
#define BM 128
#define BNT 128
#define BK 16
__global__ __launch_bounds__(256) void gemm128(
    const float* __restrict__ A, const float* __restrict__ B, float* __restrict__ C,
    int M, int N, int K, int lda, int ldb, int ldc,
    long long sA, long long sB, long long sC)
{
    __shared__ float As[BK][BM + 4];   // row stride 132 floats = 528B (16B aligned)
    __shared__ float Bs[BK][BNT + 4];
    A += (long long)blockIdx.z * sA;
    B += (long long)blockIdx.z * sB;
    C += (long long)blockIdx.z * sC;
    const int m0 = blockIdx.x * BM, n0 = blockIdx.y * BNT;
    const int tid = threadIdx.x;
    const int tx = tid & 15, ty = tid >> 4;

    // per-thread load coords (2 float4 per tile side)
    const int lrow0 = tid >> 2,        lkq0 = (tid & 3) * 4;
    const int lrow1 = (tid + 256) >> 2, lkq1 = ((tid + 256) & 3) * 4;

    unsigned long long acc[8][4];
#pragma unroll
    for (int i = 0; i < 8; i++)
#pragma unroll
        for (int j = 0; j < 4; j++) acc[i][j] = 0ull;

    float4 pa0, pa1, pb0, pb1;
    auto fetch = [&](int k0) {
        pa0 = make_float4(0.f, 0.f, 0.f, 0.f);
        pa1 = pa0; pb0 = pa0; pb1 = pa0;
        if (k0 + lkq0 < K)
            pa0 = *(const float4*)(A + (long long)(m0 + lrow0) * lda + k0 + lkq0);
        if (k0 + lkq1 < K)
            pa1 = *(const float4*)(A + (long long)(m0 + lrow1) * lda + k0 + lkq1);
        if (k0 + lkq0 < K && n0 + lrow0 < N)
            pb0 = *(const float4*)(B + (long long)(n0 + lrow0) * ldb + k0 + lkq0);
        if (k0 + lkq1 < K && n0 + lrow1 < N)
            pb1 = *(const float4*)(B + (long long)(n0 + lrow1) * ldb + k0 + lkq1);
    };

    fetch(0);
    for (int k0 = 0; k0 < K; k0 += BK) {
        As[lkq0 + 0][lrow0] = pa0.x; As[lkq0 + 1][lrow0] = pa0.y;
        As[lkq0 + 2][lrow0] = pa0.z; As[lkq0 + 3][lrow0] = pa0.w;
        As[lkq1 + 0][lrow1] = pa1.x; As[lkq1 + 1][lrow1] = pa1.y;
        As[lkq1 + 2][lrow1] = pa1.z; As[lkq1 + 3][lrow1] = pa1.w;
        Bs[lkq0 + 0][lrow0] = pb0.x; Bs[lkq0 + 1][lrow0] = pb0.y;
        Bs[lkq0 + 2][lrow0] = pb0.z; Bs[lkq0 + 3][lrow0] = pb0.w;
        Bs[lkq1 + 0][lrow1] = pb1.x; Bs[lkq1 + 1][lrow1] = pb1.y;
        Bs[lkq1 + 2][lrow1] = pb1.z; Bs[lkq1 + 3][lrow1] = pb1.w;
        __syncthreads();
        if (k0 + BK < K) fetch(k0 + BK);
#pragma unroll
        for (int kk = 0; kk < BK; kk++) {
            float4 a0 = *(const float4*)(&As[kk][ty * 4]);
            float4 a1 = *(const float4*)(&As[kk][ty * 4 + 64]);
            ulonglong2 b0 = *(const ulonglong2*)(&Bs[kk][tx * 4]);
            ulonglong2 b1 = *(const ulonglong2*)(&Bs[kk][tx * 4 + 64]);
            unsigned long long pa[8];
            pa[0] = dup2(a0.x); pa[1] = dup2(a0.y);
            pa[2] = dup2(a0.z); pa[3] = dup2(a0.w);
            pa[4] = dup2(a1.x); pa[5] = dup2(a1.y);
            pa[6] = dup2(a1.z); pa[7] = dup2(a1.w);
#pragma unroll
            for (int i = 0; i < 8; i++) {
                ffma2(acc[i][0], pa[i], b0.x);
                ffma2(acc[i][1], pa[i], b0.y);
                ffma2(acc[i][2], pa[i], b1.x);
                ffma2(acc[i][3], pa[i], b1.y);
            }
        }
        __syncthreads();
    }

#pragma unroll
    for (int ih = 0; ih < 2; ih++)
#pragma unroll
        for (int i2 = 0; i2 < 4; i2++) {
            int i = ih * 4 + i2;
            long long r = m0 + ty * 4 + ih * 64 + i2;
            int cb0 = n0 + tx * 4;
            if (cb0 < N) {
                float2 lo = unpk(acc[i][0]), hi = unpk(acc[i][1]);
                *(float4*)(C + r * ldc + cb0) = make_float4(lo.x, lo.y, hi.x, hi.y);
            }
            int cb1 = n0 + tx * 4 + 64;
            if (cb1 < N) {
                float2 lo = unpk(acc[i][2]), hi = unpk(acc[i][3]);
                *(float4*)(C + r * ldc + cb1) = make_float4(lo.x, lo.y, hi.x, hi.y);
            }
        }
}

// ---------------- extract gram diagonal -> squared norms -------------------------
__global__ void diag_norms(const float* __restrict__ dotm, float* __restrict__ nrm)
{
    int g = blockIdx.x * blockDim.x + threadIdx.x;   // 0..BN_TOT
    int b = g >> 11, i = g & 2047;
    nrm[g] = dotm[((long long)b * NPTS + i) * NPTS + i];
}

// ---------------- knn: warp per query, register top-10, shuffle merge ------------
// key: d(i,j) = |x_j|^2 - 2 x_i.x_j  (|x_i|^2 constant per i). Ties: lower j wins.
__global__ void knn_warp(const float* __restrict__ dotm, const float* __restrict__ nrm,
                         int* __restrict__ idx)
{
    int warp = (blockIdx.x * blockDim.x + threadIdx.x) >> 5;
    int lane = threadIdx.x & 31;
    int b = warp >> 11;           // / NPTS
    int i = warp & 2047;
    const float* row = dotm + ((long long)b * NPTS + i) * NPTS;   // symmetric: row i
    const float* nr = nrm + b * NPTS;

    float bd[KNN];
    int bi[KNN];
#pragma unroll
    for (int q = 0; q < KNN; q++) { bd[q] = 3.4e38f; bi[q] = 0x7fffffff; }

    for (int j = lane; j < NPTS; j += 32) {
        if (j == i) continue;
        float d = fmaf(-2.f, __ldg(row + j), __ldg(nr + j));
        if (d < bd[KNN - 1]) {              // strict: equal-d keeps earlier (smaller) j
            bd[KNN - 1] = d; bi[KNN - 1] = j;
#pragma unroll
            for (int p = KNN - 1; p > 0; p--) {
                if (bd[p] < bd[p - 1]) {    // strict: stable for ties
                    float td = bd[p]; bd[p] = bd[p - 1]; bd[p - 1] = td;
                    int tj = bi[p]; bi[p] = bi[p - 1]; bi[p - 1] = tj;
                }
            }
        }
    }

    int* o = idx + (long long)warp * KNN;
    for (int q = 0; q < KNN; q++) {
        float d0 = bd[0];
        int j0 = bi[0];
#pragma unroll
        for (int off = 16; off > 0; off >>= 1) {
            float od = __shfl_xor_sync(0xffffffffu, d0, off);
            int oj = __shfl_xor_sync(0xffffffffu, j0, off);
            if (od < d0 || (od == d0 && oj < j0)) { d0 = od; j0 = oj; }
        }
        if (lane == 0) o[q] = j0;
        if (bi[0] == j0) {                  // this lane supplied the winner: pop head
#pragma unroll
            for (int p = 0; p < KNN - 1; p++) { bd[p] = bd[p + 1]; bi[p] = bi[p + 1]; }
            bd[KNN - 1] = 3.4e38f; bi[KNN - 1] = 0x7fffffff;
        }
    }
}

// ---------------- combine: max_k(yd[j_k]) - yd[i] + yb[i], affine, lrelu ---------
__global__ void combine2(const float* __restrict__ yd, const float* __restrict__ yb,
                         const int* __restrict__ idx, const float* __restrict__ s,
                         const float* __restrict__ t, float* __restrict__ outx, int O)
{
    int g = blockIdx.x * blockDim.x + threadIdx.x;   // bn*O + o
    int bn = g / O;
    int o = g - bn * O;
    const int* ip = idx + (long long)bn * KNN;
    int base = bn & ~2047;                           // batch row base
    float m = -3.4e38f;
#pragma unroll
    for (int k = 0; k < KNN; k++) {
        int j = ip[k];
        m = fmaxf(m, yd[(long long)(base + j) * O + o]);
    }
    float h = (m - yd[g] + yb[g]) * s[o] + t[o];
    outx[(long long)bn * 512 + o] = LRELU(h);
}

// ---------------- input padding helpers -------------------------------------------
__global__ void pad_pts(const float* __restrict__ p, float* __restrict__ pp)
{
    int g = blockIdx.x * blockDim.x + threadIdx.x;   // BN_TOT
    pp[g * 4 + 0] = p[g * 3 + 0];
    pp[g * 4 + 1] = p[g * 3 + 1];
    pp[g * 4 + 2] = p[g * 3 + 2];
    pp[g * 4 + 3] = 0.f;
}
__global__ void pad_w1(const float* __restrict__ W1, float* __restrict__ wd,
                       float* __restrict__ wb)
{
    int o = threadIdx.x;   // 64
#pragma unroll
    for (int c = 0; c < 3; c++) {
        wd[o * 4 + c] = W1[o * 6 + c];
        wb[o * 4 + c] = W1[o * 6 + 3 + c];
    }
    wd[o * 4 + 3] = 0.f;
    wb[o * 4 + 3] = 0.f;
}

// ---------------- global max pool over N + affine + lrelu ------------------------
__global__ void maxpool(const float* __restrict__ H, const float* __restrict__ s5,
                        const float* __restrict__ t5, float* __restrict__ pooled)
{
    int b = blockIdx.y;
    int o = blockIdx.x * blockDim.x + threadIdx.x;   // 0..1023
    const float* p = H + (long long)b * NPTS * 1024 + o;
    float m0 = -3.4e38f, m1 = -3.4e38f, m2 = -3.4e38f, m3 = -3.4e38f;
    for (int n = 0; n < NPTS; n += 4) {
        m0 = fmaxf(m0, p[(long long)(n + 0) * 1024]);
        m1 = fmaxf(m1, p[(long long)(n + 1) * 1024]);
        m2 = fmaxf(m2, p[(long long)(n + 2) * 1024]);
        m3 = fmaxf(m3, p[(long long)(n + 3) * 1024]);
    }
    float m = fmaxf(fmaxf(m0, m1), fmaxf(m2, m3));
    float h = m * s5[o] + t5[o];
    pooled[b * 1024 + o] = LRELU(h);
}

// ---------------- final 3 FC layers, fused; one block per batch -------------------
__global__ void final_fc(const float* __restrict__ pooled,
                         const float* __restrict__ Wf1, const float* __restrict__ sf1,
                         const float* __restrict__ tf1,
                         const float* __restrict__ Wf2, const float* __restrict__ bf2,
                         const float* __restrict__ sf2, const float* __restrict__ tf2,
                         const float* __restrict__ Wf3, const float* __restrict__ bf3,
                         float* __restrict__ out)
{
    __shared__ float sx[1024];
    __shared__ float h1[512];
    __shared__ float h2[256];
    int b = blockIdx.x, tid = threadIdx.x;   // 512 threads
    sx[tid] = pooled[b * 1024 + tid];
    sx[tid + 512] = pooled[b * 1024 + tid + 512];
    __syncthreads();
    {
        const float* w = Wf1 + (long long)tid * 1024;
        float a0 = 0.f, a1 = 0.f, a2 = 0.f, a3 = 0.f;
        for (int c = 0; c < 1024; c += 4) {
            a0 = fmaf(w[c + 0], sx[c + 0], a0);
            a1 = fmaf(w[c + 1], sx[c + 1], a1);
            a2 = fmaf(w[c + 2], sx[c + 2], a2);
            a3 = fmaf(w[c + 3], sx[c + 3], a3);
        }
        float h = ((a0 + a1) + (a2 + a3)) * sf1[tid] + tf1[tid];
        h1[tid] = LRELU(h);
    }
    __syncthreads();
    if (tid < 256) {
        const float* w = Wf2 + (long long)tid * 512;
        float a0 = 0.f, a1 = 0.f, a2 = 0.f, a3 = 0.f;
        for (int c = 0; c < 512; c += 4) {
            a0 = fmaf(w[c + 0], h1[c + 0], a0);
            a1 = fmaf(w[c + 1], h1[c + 1], a1);
            a2 = fmaf(w[c + 2], h1[c + 2], a2);
            a3 = fmaf(w[c + 3], h1[c + 3], a3);
        }
        float h = (((a0 + a1) + (a2 + a3)) + bf2[tid]) * sf2[tid] + tf2[tid];
        h2[tid] = LRELU(h);
    }
    __syncthreads();
    if (tid < 3) {
        const float* w = Wf3 + (long long)tid * 256;
        float a = 0.f;
        for (int c = 0; c < 256; c++) a = fmaf(w[c], h2[c], a);
        out[b * 3 + tid] = a + bf3[tid];
    }
}

// ------------------------------- host side ---------------------------------------
extern "C" void kernel_launch(void* const* d_in, const int* in_sizes, int n_in,
                              void* d_out, int out_size)
{
    const float* points = (const float*)d_in[0];
    const float* W1 = (const float*)d_in[1];  const float* s1 = (const float*)d_in[2];  const float* t1 = (const float*)d_in[3];
    const float* W2 = (const float*)d_in[4];  const float* s2 = (const float*)d_in[5];  const float* t2 = (const float*)d_in[6];
    const float* W3 = (const float*)d_in[7];  const float* s3 = (const float*)d_in[8];  const float* t3 = (const float*)d_in[9];
    const float* W4 = (const float*)d_in[10]; const float* s4 = (const float*)d_in[11]; const float* t4 = (const float*)d_in[12];
    const float* W5 = (const float*)d_in[13]; const float* s5 = (const float*)d_in[14]; const float* t5 = (const float*)d_in[15];
    const float* Wf1 = (const float*)d_in[16]; const float* sf1 = (const float*)d_in[17]; const float* tf1 = (const float*)d_in[18];
    const float* Wf2 = (const float*)d_in[19]; const float* bf2 = (const float*)d_in[20];
    const float* sf2 = (const float*)d_in[21]; const float* tf2 = (const float*)d_in[22];
    const float* Wf3 = (const float*)d_in[23]; const float* bf3 = (const float*)d_in[24];

    float *xcat, *dotm, *nrm, *yd, *yb, *hh, *pool, *pts, *w1d, *w1b;
    int* idx;
    cudaGetSymbolAddress((void**)&xcat, g_xcat);
    cudaGetSymbolAddress((void**)&dotm, g_dot);
    cudaGetSymbolAddress((void**)&nrm,  g_nrm);
    cudaGetSymbolAddress((void**)&idx,  g_idx);
    cudaGetSymbolAddress((void**)&yd,   g_yd);
    cudaGetSymbolAddress((void**)&yb,   g_yb);
    cudaGetSymbolAddress((void**)&hh,   g_hh);
    cudaGetSymbolAddress((void**)&pool, g_pool);
    cudaGetSymbolAddress((void**)&pts,  g_pts);
    cudaGetSymbolAddress((void**)&w1d,  g_w1d);
    cudaGetSymbolAddress((void**)&w1b,  g_w1b);

    const int BN = BN_TOT;   // 16384

    pad_pts<<<BN / 256, 256>>>(points, pts);
    pad_w1<<<1, 64>>>(W1, w1d, w1b);

    // edge layer: feat (BN x C, lda), Wd/Wb (O x C, ldb), output -> xcat slice
    auto edge = [&](const float* feat, int lda, int C, int O,
                    const float* Wd, const float* Wb, int ldb,
                    const float* s, const float* t, int coff) {
        // gram per batch: Dot = X X^T
        gemm128<<<dim3(NPTS / 128, NPTS / 128, NB), 256>>>(
            feat, feat, dotm, NPTS, NPTS, C, lda, lda, NPTS,
            (long long)NPTS * lda, (long long)NPTS * lda, (long long)NPTS * NPTS);
        diag_norms<<<BN / 256, 256>>>(dotm, nrm);
        knn_warp<<<(BN * 32) / 256, 256>>>(dotm, nrm, idx);
        // yd = X @ Wd^T, yb = X @ Wb^T  (edge-conv linearity: no BNK GEMM needed)
        gemm128<<<dim3(BN / 128, (O + 127) / 128, 1), 256>>>(
            feat, Wd, yd, BN, O, C, lda, ldb, O, 0, 0, 0);
        gemm128<<<dim3(BN / 128, (O + 127) / 128, 1), 256>>>(
            feat, Wb, yb, BN, O, C, lda, ldb, O, 0, 0, 0);
        combine2<<<(BN * O) / 256, 256>>>(yd, yb, idx, s, t, xcat + coff, O);
    };

    edge(pts,        4,   4,  64, w1d,      w1b,      4,   s1, t1, 0);
    edge(xcat + 0,   512, 64,  64, W2,       W2 + 64,  128, s2, t2, 64);
    edge(xcat + 64,  512, 64, 128, W3,       W3 + 64,  128, s3, t3, 128);
    edge(xcat + 128, 512, 128, 256, W4,      W4 + 128, 256, s4, t4, 256);

    // point MLP: (16384 x 512) @ (512 x 1024)^T
    gemm128<<<dim3(BN / 128, 1024 / 128, 1), 256>>>(
        xcat, W5, hh, BN, 1024, 512, 512, 512, 1024, 0, 0, 0);
    // global max pool + affine + lrelu  (s5>0: affine/lrelu commute with max)
    maxpool<<<dim3(1024 / 256, NB), 256>>>(hh, s5, t5, pool);
    final_fc<<<NB, 512>>>(pool, Wf1, sf1, tf1, Wf2, bf2, sf2, tf2, Wf3, bf3,
                          (float*)d_out);
}

// round 4
// speedup vs baseline: 4.6472x; 1.0594x over previous
#include <cuda_runtime.h>

#define KNN 10
#define NPTS 2048
#define NB 8
#define BN_TOT (NB * NPTS)
#define LRELU(h) ((h) >= 0.f ? (h) : 0.2f * (h))

// ---------------- scratch (device globals; no runtime allocation) ----------------
__device__ float g_xcat[BN_TOT * 512];        // concat of out1..out4 (offsets 0,64,128,256)
__device__ float g_nrm[BN_TOT];               // squared row norms
__device__ int   g_idx[BN_TOT * KNN];         // knn indices
__device__ float g_yd[BN_TOT * 256];          // X @ Wdiff^T
__device__ float g_yb[BN_TOT * 256];          // X @ Wbase^T
__device__ float g_hh[BN_TOT * 1024];         // W5 output
__device__ float g_pool[NB * 1024];           // pooled features
__device__ float g_pts[BN_TOT * 4];           // points padded to C=4
__device__ float g_w1d[64 * 4];               // W1 diff half padded
__device__ float g_w1b[64 * 4];               // W1 base half padded

// ---------------- packed f32x2 helpers --------------------------------------------
__device__ __forceinline__ void ffma2(unsigned long long& d,
                                      unsigned long long a, unsigned long long b)
{
    asm("fma.rn.f32x2 %0, %1, %2, %0;" : "+l"(d) : "l"(a), "l"(b));
}
__device__ __forceinline__ unsigned long long dup2(float a)
{
    unsigned long long p;
    asm("mov.b64 %0, {%1, %1};" : "=l"(p) : "f"(a));
    return p;
}
__device__ __forceinline__ float2 unpk(unsigned long long p)
{
    float2 f;
    asm("mov.b64 {%0, %1}, %2;" : "=f"(f.x), "=f"(f.y) : "l"(p));
    return f;
}

// ================= fused gram + knn ==============================================
// One block per (128-query strip, batch). A-strip persistent in smem; sweep 16
// j-tiles of 128 computing dot tiles in regs; rank key d = nrm[j] - 2*dot kept in
// a smem stage; 4 threads/row keep running top-10 across the sweep; final 4-way
// merge with (d, j) lexicographic tie-break (matches stable top_k).
#define GK_SMEM_FLOATS (128 * 132 + 16 * 132 + 128 * 129)
#define GK_SMEM_BYTES (GK_SMEM_FLOATS * 4)
__global__ __launch_bounds__(512) void gramknn(
    const float* __restrict__ feat, int lda, int K,
    const float* __restrict__ nrm, int* __restrict__ idxout)
{
    extern __shared__ float sm[];
    float (*As)[132]    = reinterpret_cast<float(*)[132]>(sm);
    float (*Bs)[132]    = reinterpret_cast<float(*)[132]>(sm + 128 * 132);
    float (*stage)[129] = reinterpret_cast<float(*)[129]>(sm + 128 * 132 + 16 * 132);

    const int strip = blockIdx.x;            // 0..15
    const int b = blockIdx.y;                // 0..7
    const int i0 = strip * 128;
    const float* fb = feat + (long long)b * NPTS * lda;
    const float* nb = nrm + b * NPTS;
    const int tid = threadIdx.x;

    // load A strip (zero-padded to 128 k's)
    for (int e = tid; e < 128 * 128; e += 512) {
        int m = e >> 7, k = e & 127;
        As[k][m] = (k < K) ? fb[(long long)(i0 + m) * lda + k] : 0.f;
    }

    // GEMM thread map: 128x128 tile, 8 rows x 4 cols per thread
    const int cg = tid & 31;                 // col group (cols cg*4..+3)
    const int rg = tid >> 5;                 // row group (rows rg*8..+7)
    // B loader map: one float4 per thread per k-tile
    const int bjr = tid >> 2;                // 0..127 (j within tile)
    const int bkq = (tid & 3) * 4;           // k offset within k-tile

    // scan thread map: 4 threads per row
    const int srow = tid & 127;
    const int sq = tid >> 7;                 // 0..3
    const int self = i0 + srow;

    float bd[KNN];
    int bj[KNN];
#pragma unroll
    for (int p = 0; p < KNN; p++) { bd[p] = 3.4e38f; bj[p] = 0x7fffffff; }

    const int gKT = (K + 15) >> 4;

    for (int jt = 0; jt < 16; jt++) {
        const int j0 = jt * 128;

        unsigned long long acc[8][2];
#pragma unroll
        for (int r = 0; r < 8; r++) { acc[r][0] = 0ull; acc[r][1] = 0ull; }

        float4 pb = make_float4(0.f, 0.f, 0.f, 0.f);
        if (bkq < K)
            pb = *(const float4*)(fb + (long long)(j0 + bjr) * lda + bkq);

        for (int kt = 0; kt < gKT; kt++) {
            __syncthreads();
            Bs[bkq + 0][bjr] = pb.x; Bs[bkq + 1][bjr] = pb.y;
            Bs[bkq + 2][bjr] = pb.z; Bs[bkq + 3][bjr] = pb.w;
            __syncthreads();
            if (kt + 1 < gKT) {
                int k0 = kt * 16 + 16;
                pb = make_float4(0.f, 0.f, 0.f, 0.f);
                if (k0 + bkq < K)
                    pb = *(const float4*)(fb + (long long)(j0 + bjr) * lda + k0 + bkq);
            }
            const int kb = kt * 16;
#pragma unroll
            for (int kk = 0; kk < 16; kk++) {
                float4 a0 = *(const float4*)(&As[kb + kk][rg * 8]);
                float4 a1 = *(const float4*)(&As[kb + kk][rg * 8 + 4]);
                ulonglong2 bb = *(const ulonglong2*)(&Bs[kk][cg * 4]);
                unsigned long long pa;
                pa = dup2(a0.x); ffma2(acc[0][0], pa, bb.x); ffma2(acc[0][1], pa, bb.y);
                pa = dup2(a0.y); ffma2(acc[1][0], pa, bb.x); ffma2(acc[1][1], pa, bb.y);
                pa = dup2(a0.z); ffma2(acc[2][0], pa, bb.x); ffma2(acc[2][1], pa, bb.y);
                pa = dup2(a0.w); ffma2(acc[3][0], pa, bb.x); ffma2(acc[3][1], pa, bb.y);
                pa = dup2(a1.x); ffma2(acc[4][0], pa, bb.x); ffma2(acc[4][1], pa, bb.y);
                pa = dup2(a1.y); ffma2(acc[5][0], pa, bb.x); ffma2(acc[5][1], pa, bb.y);
                pa = dup2(a1.z); ffma2(acc[6][0], pa, bb.x); ffma2(acc[6][1], pa, bb.y);
                pa = dup2(a1.w); ffma2(acc[7][0], pa, bb.x); ffma2(acc[7][1], pa, bb.y);
            }
        }

        // write rank keys d = nrm[j] - 2*dot into stage
        float4 nj = *(const float4*)(nb + j0 + cg * 4);
#pragma unroll
        for (int r = 0; r < 8; r++) {
            int m = rg * 8 + r;
            float2 lo = unpk(acc[r][0]);
            float2 hi = unpk(acc[r][1]);
            float* sr = &stage[m][cg * 4];
            sr[0] = fmaf(-2.f, lo.x, nj.x);
            sr[1] = fmaf(-2.f, lo.y, nj.y);
            sr[2] = fmaf(-2.f, hi.x, nj.z);
            sr[3] = fmaf(-2.f, hi.y, nj.w);
        }
        __syncthreads();

        // scan: this thread's 32 cols of its row, running top-10
        for (int c = sq * 32; c < sq * 32 + 32; c++) {
            float d = stage[srow][c];
            int j = j0 + c;
            if (j != self && d < bd[KNN - 1]) {   // strict <: ascending-j stability
                bd[KNN - 1] = d; bj[KNN - 1] = j;
#pragma unroll
                for (int p = KNN - 1; p > 0; p--) {
                    if (bd[p] < bd[p - 1]) {
                        float td = bd[p]; bd[p] = bd[p - 1]; bd[p - 1] = td;
                        int tj = bj[p]; bj[p] = bj[p - 1]; bj[p - 1] = tj;
                    }
                }
            }
        }
        __syncthreads();   // scans done before next tile overwrites stage
    }

    // dump lists to smem (stride 24: d[0..10] sentinel at 10, j at 12..22)
    float* mb = &stage[0][0];
    {
        int base = (srow * 4 + sq) * 24;
#pragma unroll
        for (int p = 0; p < KNN; p++) {
            mb[base + p] = bd[p];
            ((int*)mb)[base + 12 + p] = bj[p];
        }
        mb[base + KNN] = 3.4e38f;
        ((int*)mb)[base + 12 + KNN] = 0x7fffffff;
    }
    __syncthreads();

    if (tid < 128) {
        int row = tid;
        int ptr[4] = {0, 0, 0, 0};
        int* outp = idxout + ((long long)(b * NPTS + i0 + row)) * KNN;
#pragma unroll
        for (int q = 0; q < KNN; q++) {
            float bestd = 3.4e38f; int bestj = 0x7fffffff; int bl = 0;
#pragma unroll
            for (int l = 0; l < 4; l++) {
                int base = (row * 4 + l) * 24;
                float dl = mb[base + ptr[l]];
                int jl = ((int*)mb)[base + 12 + ptr[l]];
                if (dl < bestd || (dl == bestd && jl < bestj)) {
                    bestd = dl; bestj = jl; bl = l;
                }
            }
            outp[q] = bestj;
            ptr[bl]++;
        }
    }
}

// ---------------- row squared norms ------------------------------------------------
__global__ void rownorms(const float* __restrict__ feat, int lda, int C,
                         float* __restrict__ nrm)
{
    int g = blockIdx.x * blockDim.x + threadIdx.x;   // BN_TOT
    const float* p = feat + (long long)g * lda;
    float s = 0.f;
    for (int c = 0; c < C; c += 4) {
        float4 v = *(const float4*)(p + c);
        s += v.x * v.x + v.y * v.y + v.z * v.z + v.w * v.w;
    }
    nrm[g] = s;
}

// ================= 128x128 GEMM, 8x8 micro-tile, FFMA2 math, NT form =============
// C[m][n] = sum_k A[m][k]*B[n][k].  M % 128 == 0.  N col-guarded. K % 4 == 0.
#define BM 128
#define BNT 128
#define BK 16
__global__ __launch_bounds__(256) void gemm128(
    const float* __restrict__ A, const float* __restrict__ B, float* __restrict__ C,
    int M, int N, int K, int lda, int ldb, int ldc,
    long long sA, long long sB, long long sC)
{
    __shared__ float As[BK][BM + 4];
    __shared__ float Bs[BK][BNT + 4];
    A += (long long)blockIdx.z * sA;
    B += (long long)blockIdx.z * sB;
    C += (long long)blockIdx.z * sC;
    const int m0 = blockIdx.x * BM, n0 = blockIdx.y * BNT;
    const int tid = threadIdx.x;
    const int tx = tid & 15, ty = tid >> 4;

    const int lrow0 = tid >> 2,        lkq0 = (tid & 3) * 4;
    const int lrow1 = (tid + 256) >> 2, lkq1 = ((tid + 256) & 3) * 4;

    unsigned long long acc[8][4];
#pragma unroll
    for (int i = 0; i < 8; i++)
#pragma unroll
        for (int j = 0; j < 4; j++) acc[i][j] = 0ull;

    float4 pa0, pa1, pb0, pb1;
    auto fetch = [&](int k0) {
        pa0 = make_float4(0.f, 0.f, 0.f, 0.f);
        pa1 = pa0; pb0 = pa0; pb1 = pa0;
        if (k0 + lkq0 < K)
            pa0 = *(const float4*)(A + (long long)(m0 + lrow0) * lda + k0 + lkq0);
        if (k0 + lkq1 < K)
            pa1 = *(const float4*)(A + (long long)(m0 + lrow1) * lda + k0 + lkq1);
        if (k0 + lkq0 < K && n0 + lrow0 < N)
            pb0 = *(const float4*)(B + (long long)(n0 + lrow0) * ldb + k0 + lkq0);
        if (k0 + lkq1 < K && n0 + lrow1 < N)
            pb1 = *(const float4*)(B + (long long)(n0 + lrow1) * ldb + k0 + lkq1);
    };

    fetch(0);
    for (int k0 = 0; k0 < K; k0 += BK) {
        As[lkq0 + 0][lrow0] = pa0.x; As[lkq0 + 1][lrow0] = pa0.y;
        As[lkq0 + 2][lrow0] = pa0.z; As[lkq0 + 3][lrow0] = pa0.w;
        As[lkq1 + 0][lrow1] = pa1.x; As[lkq1 + 1][lrow1] = pa1.y;
        As[lkq1 + 2][lrow1] = pa1.z; As[lkq1 + 3][lrow1] = pa1.w;
        Bs[lkq0 + 0][lrow0] = pb0.x; Bs[lkq0 + 1][lrow0] = pb0.y;
        Bs[lkq0 + 2][lrow0] = pb0.z; Bs[lkq0 + 3][lrow0] = pb0.w;
        Bs[lkq1 + 0][lrow1] = pb1.x; Bs[lkq1 + 1][lrow1] = pb1.y;
        Bs[lkq1 + 2][lrow1] = pb1.z; Bs[lkq1 + 3][lrow1] = pb1.w;
        __syncthreads();
        if (k0 + BK < K) fetch(k0 + BK);
#pragma unroll
        for (int kk = 0; kk < BK; kk++) {
            float4 a0 = *(const float4*)(&As[kk][ty * 4]);
            float4 a1 = *(const float4*)(&As[kk][ty * 4 + 64]);
            ulonglong2 b0 = *(const ulonglong2*)(&Bs[kk][tx * 4]);
            ulonglong2 b1 = *(const ulonglong2*)(&Bs[kk][tx * 4 + 64]);
            unsigned long long pa[8];
            pa[0] = dup2(a0.x); pa[1] = dup2(a0.y);
            pa[2] = dup2(a0.z); pa[3] = dup2(a0.w);
            pa[4] = dup2(a1.x); pa[5] = dup2(a1.y);
            pa[6] = dup2(a1.z); pa[7] = dup2(a1.w);
#pragma unroll
            for (int i = 0; i < 8; i++) {
                ffma2(acc[i][0], pa[i], b0.x);
                ffma2(acc[i][1], pa[i], b0.y);
                ffma2(acc[i][2], pa[i], b1.x);
                ffma2(acc[i][3], pa[i], b1.y);
            }
        }
        __syncthreads();
    }

#pragma unroll
    for (int ih = 0; ih < 2; ih++)
#pragma unroll
        for (int i2 = 0; i2 < 4; i2++) {
            int i = ih * 4 + i2;
            long long r = m0 + ty * 4 + ih * 64 + i2;
            int cb0 = n0 + tx * 4;
            if (cb0 < N) {
                float2 lo = unpk(acc[i][0]), hi = unpk(acc[i][1]);
                *(float4*)(C + r * ldc + cb0) = make_float4(lo.x, lo.y, hi.x, hi.y);
            }
            int cb1 = n0 + tx * 4 + 64;
            if (cb1 < N) {
                float2 lo = unpk(acc[i][2]), hi = unpk(acc[i][3]);
                *(float4*)(C + r * ldc + cb1) = make_float4(lo.x, lo.y, hi.x, hi.y);
            }
        }
}

// ---------------- combine: max_k(yd[j_k]) - yd[i] + yb[i], affine, lrelu ---------
__global__ void combine2(const float* __restrict__ yd, const float* __restrict__ yb,
                         const int* __restrict__ idx, const float* __restrict__ s,
                         const float* __restrict__ t, float* __restrict__ outx, int O)
{
    int g = blockIdx.x * blockDim.x + threadIdx.x;   // bn*O + o
    int bn = g / O;
    int o = g - bn * O;
    const int* ip = idx + (long long)bn * KNN;
    int base = bn & ~2047;                           // batch row base
    float m = -3.4e38f;
#pragma unroll
    for (int k = 0; k < KNN; k++) {
        int j = ip[k];
        m = fmaxf(m, yd[(long long)(base + j) * O + o]);
    }
    float h = (m - yd[g] + yb[g]) * s[o] + t[o];
    outx[(long long)bn * 512 + o] = LRELU(h);
}

// ---------------- input padding helpers -------------------------------------------
__global__ void pad_pts(const float* __restrict__ p, float* __restrict__ pp)
{
    int g = blockIdx.x * blockDim.x + threadIdx.x;   // BN_TOT
    pp[g * 4 + 0] = p[g * 3 + 0];
    pp[g * 4 + 1] = p[g * 3 + 1];
    pp[g * 4 + 2] = p[g * 3 + 2];
    pp[g * 4 + 3] = 0.f;
}
__global__ void pad_w1(const float* __restrict__ W1, float* __restrict__ wd,
                       float* __restrict__ wb)
{
    int o = threadIdx.x;   // 64
#pragma unroll
    for (int c = 0; c < 3; c++) {
        wd[o * 4 + c] = W1[o * 6 + c];
        wb[o * 4 + c] = W1[o * 6 + 3 + c];
    }
    wd[o * 4 + 3] = 0.f;
    wb[o * 4 + 3] = 0.f;
}

// ---------------- global max pool over N + affine + lrelu ------------------------
__global__ void maxpool(const float* __restrict__ H, const float* __restrict__ s5,
                        const float* __restrict__ t5, float* __restrict__ pooled)
{
    int b = blockIdx.y;
    int o = blockIdx.x * blockDim.x + threadIdx.x;   // 0..1023
    const float* p = H + (long long)b * NPTS * 1024 + o;
    float m0 = -3.4e38f, m1 = -3.4e38f, m2 = -3.4e38f, m3 = -3.4e38f;
    for (int n = 0; n < NPTS; n += 4) {
        m0 = fmaxf(m0, p[(long long)(n + 0) * 1024]);
        m1 = fmaxf(m1, p[(long long)(n + 1) * 1024]);
        m2 = fmaxf(m2, p[(long long)(n + 2) * 1024]);
        m3 = fmaxf(m3, p[(long long)(n + 3) * 1024]);
    }
    float m = fmaxf(fmaxf(m0, m1), fmaxf(m2, m3));
    float h = m * s5[o] + t5[o];
    pooled[b * 1024 + o] = LRELU(h);
}

// ---------------- final 3 FC layers, fused; one block per batch -------------------
__global__ void final_fc(const float* __restrict__ pooled,
                         const float* __restrict__ Wf1, const float* __restrict__ sf1,
                         const float* __restrict__ tf1,
                         const float* __restrict__ Wf2, const float* __restrict__ bf2,
                         const float* __restrict__ sf2, const float* __restrict__ tf2,
                         const float* __restrict__ Wf3, const float* __restrict__ bf3,
                         float* __restrict__ out)
{
    __shared__ float sx[1024];
    __shared__ float h1[512];
    __shared__ float h2[256];
    int b = blockIdx.x, tid = threadIdx.x;   // 512 threads
    sx[tid] = pooled[b * 1024 + tid];
    sx[tid + 512] = pooled[b * 1024 + tid + 512];
    __syncthreads();
    {
        const float* w = Wf1 + (long long)tid * 1024;
        float a0 = 0.f, a1 = 0.f, a2 = 0.f, a3 = 0.f;
        for (int c = 0; c < 1024; c += 4) {
            a0 = fmaf(w[c + 0], sx[c + 0], a0);
            a1 = fmaf(w[c + 1], sx[c + 1], a1);
            a2 = fmaf(w[c + 2], sx[c + 2], a2);
            a3 = fmaf(w[c + 3], sx[c + 3], a3);
        }
        float h = ((a0 + a1) + (a2 + a3)) * sf1[tid] + tf1[tid];
        h1[tid] = LRELU(h);
    }
    __syncthreads();
    if (tid < 256) {
        const float* w = Wf2 + (long long)tid * 512;
        float a0 = 0.f, a1 = 0.f, a2 = 0.f, a3 = 0.f;
        for (int c = 0; c < 512; c += 4) {
            a0 = fmaf(w[c + 0], h1[c + 0], a0);
            a1 = fmaf(w[c + 1], h1[c + 1], a1);
            a2 = fmaf(w[c + 2], h1[c + 2], a2);
            a3 = fmaf(w[c + 3], h1[c + 3], a3);
        }
        float h = (((a0 + a1) + (a2 + a3)) + bf2[tid]) * sf2[tid] + tf2[tid];
        h2[tid] = LRELU(h);
    }
    __syncthreads();
    if (tid < 3) {
        const float* w = Wf3 + (long long)tid * 256;
        float a = 0.f;
        for (int c = 0; c < 256; c++) a = fmaf(w[c], h2[c], a);
        out[b * 3 + tid] = a + bf3[tid];
    }
}

// ------------------------------- host side ---------------------------------------
extern "C" void kernel_launch(void* const* d_in, const int* in_sizes, int n_in,
                              void* d_out, int out_size)
{
    const float* points = (const float*)d_in[0];
    const float* W1 = (const float*)d_in[1];  const float* s1 = (const float*)d_in[2];  const float* t1 = (const float*)d_in[3];
    const float* W2 = (const float*)d_in[4];  const float* s2 = (const float*)d_in[5];  const float* t2 = (const float*)d_in[6];
    const float* W3 = (const float*)d_in[7];  const float* s3 = (const float*)d_in[8];  const float* t3 = (const float*)d_in[9];
    const float* W4 = (const float*)d_in[10]; const float* s4 = (const float*)d_in[11]; const float* t4 = (const float*)d_in[12];
    const float* W5 = (const float*)d_in[13]; const float* s5 = (const float*)d_in[14]; const float* t5 = (const float*)d_in[15];
    const float* Wf1 = (const float*)d_in[16]; const float* sf1 = (const float*)d_in[17]; const float* tf1 = (const float*)d_in[18];
    const float* Wf2 = (const float*)d_in[19]; const float* bf2 = (const float*)d_in[20];
    const float* sf2 = (const float*)d_in[21]; const float* tf2 = (const float*)d_in[22];
    const float* Wf3 = (const float*)d_in[23]; const float* bf3 = (const float*)d_in[24];

    float *xcat, *nrm, *yd, *yb, *hh, *pool, *pts, *w1d, *w1b;
    int* idx;
    cudaGetSymbolAddress((void**)&xcat, g_xcat);
    cudaGetSymbolAddress((void**)&nrm,  g_nrm);
    cudaGetSymbolAddress((void**)&idx,  g_idx);
    cudaGetSymbolAddress((void**)&yd,   g_yd);
    cudaGetSymbolAddress((void**)&yb,   g_yb);
    cudaGetSymbolAddress((void**)&hh,   g_hh);
    cudaGetSymbolAddress((void**)&pool, g_pool);
    cudaGetSymbolAddress((void**)&pts,  g_pts);
    cudaGetSymbolAddress((void**)&w1d,  g_w1d);
    cudaGetSymbolAddress((void**)&w1b,  g_w1b);

    cudaFuncSetAttribute(gramknn, cudaFuncAttributeMaxDynamicSharedMemorySize,
                         GK_SMEM_BYTES);

    const int BN = BN_TOT;   // 16384

    pad_pts<<<BN / 256, 256>>>(points, pts);
    pad_w1<<<1, 64>>>(W1, w1d, w1b);

    // edge layer: feat (BN x C, lda), Wd/Wb (O x C, ldb), output -> xcat slice
    auto edge = [&](const float* feat, int lda, int C, int O,
                    const float* Wd, const float* Wb, int ldb,
                    const float* s, const float* t, int coff) {
        rownorms<<<BN / 256, 256>>>(feat, lda, C, nrm);
        gramknn<<<dim3(16, NB), 512, GK_SMEM_BYTES>>>(feat, lda, C, nrm, idx);
        // yd = X @ Wd^T, yb = X @ Wb^T  (edge-conv linearity: no BNK GEMM needed)
        gemm128<<<dim3(BN / 128, (O + 127) / 128, 1), 256>>>(
            feat, Wd, yd, BN, O, C, lda, ldb, O, 0, 0, 0);
        gemm128<<<dim3(BN / 128, (O + 127) / 128, 1), 256>>>(
            feat, Wb, yb, BN, O, C, lda, ldb, O, 0, 0, 0);
        combine2<<<(BN * O) / 256, 256>>>(yd, yb, idx, s, t, xcat + coff, O);
    };

    edge(pts,        4,   4,  64, w1d,      w1b,      4,   s1, t1, 0);
    edge(xcat + 0,   512, 64,  64, W2,       W2 + 64,  128, s2, t2, 64);
    edge(xcat + 64,  512, 64, 128, W3,       W3 + 64,  128, s3, t3, 128);
    edge(xcat + 128, 512, 128, 256, W4,      W4 + 128, 256, s4, t4, 256);

    // point MLP: (16384 x 512) @ (512 x 1024)^T
    gemm128<<<dim3(BN / 128, 1024 / 128, 1), 256>>>(
        xcat, W5, hh, BN, 1024, 512, 512, 512, 1024, 0, 0, 0);
    // global max pool + affine + lrelu  (s5>0: affine/lrelu commute with max)
    maxpool<<<dim3(1024 / 256, NB), 256>>>(hh, s5, t5, pool);
    final_fc<<<NB, 512>>>(pool, Wf1, sf1, tf1, Wf2, bf2, sf2, tf2, Wf3, bf3,
                          (float*)d_out);
}

// round 6
// speedup vs baseline: 4.7541x; 1.0230x over previous
#include <cuda_runtime.h>
#include <cuda_bf16.h>
#include <stdint.h>

#define KNN 10
#define NPTS 2048
#define NB 8
#define BN_TOT (NB * NPTS)
#define LRELU(h) ((h) >= 0.f ? (h) : 0.2f * (h))

// ---------------- scratch (device globals; no runtime allocation) ----------------
__device__ float g_xcat[BN_TOT * 512];        // concat of out1..out4
__device__ float g_nrm[BN_TOT];
__device__ int   g_idx[BN_TOT * KNN];
__device__ float g_ycomb[BN_TOT * 512];       // [yd | yb] stacked cols (max 2*256)
__device__ float g_hh[BN_TOT * 1024];
__device__ float g_pool[NB * 1024];
__device__ float g_pts[BN_TOT * 4];
__device__ float g_w1d[64 * 4];
__device__ float g_w1b[64 * 4];
__device__ __nv_bfloat16 g_a3[BN_TOT * 1536]; // split A (hi|lo|hi), max Kp=1536
__device__ __nv_bfloat16 g_w3[1024 * 1536];   // split W (hi|hi|lo)

// ---------------- packed f32x2 helpers (gramknn) ----------------------------------
__device__ __forceinline__ void ffma2(unsigned long long& d,
                                      unsigned long long a, unsigned long long b)
{
    asm("fma.rn.f32x2 %0, %1, %2, %0;" : "+l"(d) : "l"(a), "l"(b));
}
__device__ __forceinline__ unsigned long long dup2(float a)
{
    unsigned long long p;
    asm("mov.b64 %0, {%1, %1};" : "=l"(p) : "f"(a));
    return p;
}
__device__ __forceinline__ float2 unpk(unsigned long long p)
{
    float2 f;
    asm("mov.b64 {%0, %1}, %2;" : "=f"(f.x), "=f"(f.y) : "l"(p));
    return f;
}

// ---------------- mma.sync helpers -------------------------------------------------
__device__ __forceinline__ uint32_t smem_u32(const void* p)
{
    uint32_t a;
    asm("{ .reg .u64 t; cvta.to.shared.u64 t, %1; cvt.u32.u64 %0, t; }"
        : "=r"(a) : "l"(p));
    return a;
}
__device__ __forceinline__ void ldm_x4(uint32_t& r0, uint32_t& r1,
                                       uint32_t& r2, uint32_t& r3, uint32_t addr)
{
    asm volatile("ldmatrix.sync.aligned.m8n8.x4.shared.b16 {%0,%1,%2,%3}, [%4];"
                 : "=r"(r0), "=r"(r1), "=r"(r2), "=r"(r3) : "r"(addr));
}
__device__ __forceinline__ void mma16816(float* d, const uint32_t* a, const uint32_t* b)
{
    asm volatile(
        "mma.sync.aligned.m16n8k16.row.col.f32.bf16.bf16.f32 "
        "{%0,%1,%2,%3}, {%4,%5,%6,%7}, {%8,%9}, {%0,%1,%2,%3};"
        : "+f"(d[0]), "+f"(d[1]), "+f"(d[2]), "+f"(d[3])
        : "r"(a[0]), "r"(a[1]), "r"(a[2]), "r"(a[3]), "r"(b[0]), "r"(b[1]));
}

// ================= HMMA bf16 NT GEMM =============================================
// C[m][n] = sum_k A[m][k] * B[n][k]. fp32 out.
// CTA 128x128, 8 warps (2x4), warp tile 64x32 (4x4 of m16n8k16), BK=32.
// Requires: M % 128 == 0, N % 128 == 0, Kp % 32 == 0. No guards in hot loop.
#define HS 40   // smem row stride in bf16 (80B: conflict-free ldmatrix)
__global__ __launch_bounds__(256) void hgemm(
    const __nv_bfloat16* __restrict__ A, const __nv_bfloat16* __restrict__ B,
    float* __restrict__ C, int M, int N, int Kp, int ldc)
{
    __shared__ __nv_bfloat16 As[2][128][HS];
    __shared__ __nv_bfloat16 Bs[2][128][HS];
    const int tid = threadIdx.x;
    const int wid = tid >> 5, lane = tid & 31;
    const int wm = wid >> 2, wn = wid & 3;         // 2 x 4 warp grid
    const int m0 = blockIdx.x * 128, n0 = blockIdx.y * 128;

    // loader: 512 16B-chunks per matrix, 2 per thread
    const int lrow = tid >> 2, lkc = (tid & 3) * 8;

    float acc[4][4][4];
#pragma unroll
    for (int i = 0; i < 4; i++)
#pragma unroll
        for (int j = 0; j < 4; j++)
#pragma unroll
            for (int q = 0; q < 4; q++) acc[i][j][q] = 0.f;

    uint4 va0, va1, vb0, vb1;
    const __nv_bfloat16* arow0 = A + (long long)(m0 + lrow) * Kp + lkc;
    const __nv_bfloat16* arow1 = arow0 + (long long)64 * Kp;
    const __nv_bfloat16* brow0 = B + (long long)(n0 + lrow) * Kp + lkc;
    const __nv_bfloat16* brow1 = brow0 + (long long)64 * Kp;

    va0 = *(const uint4*)(arow0);
    va1 = *(const uint4*)(arow1);
    vb0 = *(const uint4*)(brow0);
    vb1 = *(const uint4*)(brow1);
    *(uint4*)(&As[0][lrow][lkc]) = va0;
    *(uint4*)(&As[0][lrow + 64][lkc]) = va1;
    *(uint4*)(&Bs[0][lrow][lkc]) = vb0;
    *(uint4*)(&Bs[0][lrow + 64][lkc]) = vb1;
    __syncthreads();

    const int nc = Kp >> 5;

    // precompute ldmatrix smem addresses (stage 0; stage 1 = +stage offset)
    const uint32_t aoff = (uint32_t)(((char*)&As[1][0][0]) - ((char*)&As[0][0][0]));
    const int arow_f = wm * 64 + (lane & 15);
    const int ahalf = (lane >> 4) * 8;
    const int bgrp = lane >> 3;
    const int brow_base = wn * 32 + (lane & 7);
    const int bhalf = (bgrp & 1) * 8;

    for (int c = 0; c < nc; c++) {
        const int cur = c & 1;
        if (c + 1 < nc) {
            const int k1 = (c + 1) * 32;
            va0 = *(const uint4*)(arow0 + k1);
            va1 = *(const uint4*)(arow1 + k1);
            vb0 = *(const uint4*)(brow0 + k1);
            vb1 = *(const uint4*)(brow1 + k1);
        }
#pragma unroll
        for (int ks = 0; ks < 2; ks++) {
            uint32_t af[4][4], bf[4][2];
#pragma unroll
            for (int mt = 0; mt < 4; mt++) {
                uint32_t ad = smem_u32(&As[cur][arow_f + mt * 16][ks * 16 + ahalf]);
                ldm_x4(af[mt][0], af[mt][1], af[mt][2], af[mt][3], ad);
            }
#pragma unroll
            for (int p = 0; p < 2; p++) {
                int brow = brow_base + (p * 2 + (bgrp >> 1)) * 8;
                uint32_t bd = smem_u32(&Bs[cur][brow][ks * 16 + bhalf]);
                ldm_x4(bf[p * 2][0], bf[p * 2][1], bf[p * 2 + 1][0], bf[p * 2 + 1][1], bd);
            }
#pragma unroll
            for (int mt = 0; mt < 4; mt++)
#pragma unroll
                for (int nt = 0; nt < 4; nt++)
                    mma16816(acc[mt][nt], af[mt], bf[nt]);
        }
        __syncthreads();
        if (c + 1 < nc) {
            const int nxt = (c + 1) & 1;
            *(uint4*)(&As[nxt][lrow][lkc]) = va0;
            *(uint4*)(&As[nxt][lrow + 64][lkc]) = va1;
            *(uint4*)(&Bs[nxt][lrow][lkc]) = vb0;
            *(uint4*)(&Bs[nxt][lrow + 64][lkc]) = vb1;
            __syncthreads();
        }
    }

    // epilogue
#pragma unroll
    for (int mt = 0; mt < 4; mt++) {
        int row = m0 + wm * 64 + mt * 16 + (lane >> 2);
#pragma unroll
        for (int nt = 0; nt < 4; nt++) {
            int col = n0 + wn * 32 + nt * 8 + (lane & 3) * 2;
            *(float2*)(C + (long long)row * ldc + col) =
                make_float2(acc[mt][nt][0], acc[mt][nt][1]);
            *(float2*)(C + (long long)(row + 8) * ldc + col) =
                make_float2(acc[mt][nt][2], acc[mt][nt][3]);
        }
    }
}

// ---------------- split fp32 -> bf16 [hi|lo|hi], zero-padded to Kp ----------------
__global__ void split3_feat(const float* __restrict__ src, int lda, int C, int Kp,
                            __nv_bfloat16* __restrict__ dst, long long total)
{
    long long g = (long long)blockIdx.x * blockDim.x + threadIdx.x;
    if (g >= total) return;
    int k = (int)(g % Kp);
    long long m = g / Kp;
    if (k < 3 * C) {
        int seg = k / C, c = k - seg * C;
        float x = src[m * lda + c];
        __nv_bfloat16 hi = __float2bfloat16(x);
        if (seg == 1) dst[g] = __float2bfloat16(x - __bfloat162float(hi));
        else dst[g] = hi;
        return;
    }
    dst[g] = __float2bfloat16(0.f);
}
// W rows: [hi|hi|lo]
__global__ void split3_w(const float* __restrict__ src, int lds, int C, int Kp,
                         __nv_bfloat16* __restrict__ dst, int rowoff, long long total)
{
    long long g = (long long)blockIdx.x * blockDim.x + threadIdx.x;
    if (g >= total) return;
    int k = (int)(g % Kp);
    long long o = g / Kp;
    __nv_bfloat16* d = dst + (rowoff + o) * (long long)Kp + k;
    if (k < 3 * C) {
        int seg = k / C, c = k - seg * C;
        float x = src[o * lds + c];
        __nv_bfloat16 hi = __float2bfloat16(x);
        if (seg == 2) *d = __float2bfloat16(x - __bfloat162float(hi));
        else *d = hi;
        return;
    }
    *d = __float2bfloat16(0.f);
}

// ================= fused gram + knn (unchanged from R4) ==========================
#define GK_SMEM_FLOATS (128 * 132 + 16 * 132 + 128 * 129)
#define GK_SMEM_BYTES (GK_SMEM_FLOATS * 4)
__global__ __launch_bounds__(512) void gramknn(
    const float* __restrict__ feat, int lda, int K,
    const float* __restrict__ nrm, int* __restrict__ idxout)
{
    extern __shared__ float sm[];
    float (*As)[132]    = reinterpret_cast<float(*)[132]>(sm);
    float (*Bs)[132]    = reinterpret_cast<float(*)[132]>(sm + 128 * 132);
    float (*stage)[129] = reinterpret_cast<float(*)[129]>(sm + 128 * 132 + 16 * 132);

    const int strip = blockIdx.x;
    const int b = blockIdx.y;
    const int i0 = strip * 128;
    const float* fb = feat + (long long)b * NPTS * lda;
    const float* nb = nrm + b * NPTS;
    const int tid = threadIdx.x;

    for (int e = tid; e < 128 * 128; e += 512) {
        int m = e >> 7, k = e & 127;
        As[k][m] = (k < K) ? fb[(long long)(i0 + m) * lda + k] : 0.f;
    }

    const int cg = tid & 31;
    const int rg = tid >> 5;
    const int bjr = tid >> 2;
    const int bkq = (tid & 3) * 4;
    const int srow = tid & 127;
    const int sq = tid >> 7;
    const int self = i0 + srow;

    float bd[KNN];
    int bj[KNN];
#pragma unroll
    for (int p = 0; p < KNN; p++) { bd[p] = 3.4e38f; bj[p] = 0x7fffffff; }

    const int gKT = (K + 15) >> 4;

    for (int jt = 0; jt < 16; jt++) {
        const int j0 = jt * 128;
        unsigned long long acc[8][2];
#pragma unroll
        for (int r = 0; r < 8; r++) { acc[r][0] = 0ull; acc[r][1] = 0ull; }

        float4 pb = make_float4(0.f, 0.f, 0.f, 0.f);
        if (bkq < K)
            pb = *(const float4*)(fb + (long long)(j0 + bjr) * lda + bkq);

        for (int kt = 0; kt < gKT; kt++) {
            __syncthreads();
            Bs[bkq + 0][bjr] = pb.x; Bs[bkq + 1][bjr] = pb.y;
            Bs[bkq + 2][bjr] = pb.z; Bs[bkq + 3][bjr] = pb.w;
            __syncthreads();
            if (kt + 1 < gKT) {
                int k0 = kt * 16 + 16;
                pb = make_float4(0.f, 0.f, 0.f, 0.f);
                if (k0 + bkq < K)
                    pb = *(const float4*)(fb + (long long)(j0 + bjr) * lda + k0 + bkq);
            }
            const int kb = kt * 16;
#pragma unroll
            for (int kk = 0; kk < 16; kk++) {
                float4 a0 = *(const float4*)(&As[kb + kk][rg * 8]);
                float4 a1 = *(const float4*)(&As[kb + kk][rg * 8 + 4]);
                ulonglong2 bb = *(const ulonglong2*)(&Bs[kk][cg * 4]);
                unsigned long long pa;
                pa = dup2(a0.x); ffma2(acc[0][0], pa, bb.x); ffma2(acc[0][1], pa, bb.y);
                pa = dup2(a0.y); ffma2(acc[1][0], pa, bb.x); ffma2(acc[1][1], pa, bb.y);
                pa = dup2(a0.z); ffma2(acc[2][0], pa, bb.x); ffma2(acc[2][1], pa, bb.y);
                pa = dup2(a0.w); ffma2(acc[3][0], pa, bb.x); ffma2(acc[3][1], pa, bb.y);
                pa = dup2(a1.x); ffma2(acc[4][0], pa, bb.x); ffma2(acc[4][1], pa, bb.y);
                pa = dup2(a1.y); ffma2(acc[5][0], pa, bb.x); ffma2(acc[5][1], pa, bb.y);
                pa = dup2(a1.z); ffma2(acc[6][0], pa, bb.x); ffma2(acc[6][1], pa, bb.y);
                pa = dup2(a1.w); ffma2(acc[7][0], pa, bb.x); ffma2(acc[7][1], pa, bb.y);
            }
        }

        float4 nj = *(const float4*)(nb + j0 + cg * 4);
#pragma unroll
        for (int r = 0; r < 8; r++) {
            int m = rg * 8 + r;
            float2 lo = unpk(acc[r][0]);
            float2 hi = unpk(acc[r][1]);
            float* sr = &stage[m][cg * 4];
            sr[0] = fmaf(-2.f, lo.x, nj.x);
            sr[1] = fmaf(-2.f, lo.y, nj.y);
            sr[2] = fmaf(-2.f, hi.x, nj.z);
            sr[3] = fmaf(-2.f, hi.y, nj.w);
        }
        __syncthreads();

        for (int c = sq * 32; c < sq * 32 + 32; c++) {
            float d = stage[srow][c];
            int j = j0 + c;
            if (j != self && d < bd[KNN - 1]) {
                bd[KNN - 1] = d; bj[KNN - 1] = j;
#pragma unroll
                for (int p = KNN - 1; p > 0; p--) {
                    if (bd[p] < bd[p - 1]) {
                        float td = bd[p]; bd[p] = bd[p - 1]; bd[p - 1] = td;
                        int tj = bj[p]; bj[p] = bj[p - 1]; bj[p - 1] = tj;
                    }
                }
            }
        }
        __syncthreads();
    }

    float* mb = &stage[0][0];
    {
        int base = (srow * 4 + sq) * 24;
#pragma unroll
        for (int p = 0; p < KNN; p++) {
            mb[base + p] = bd[p];
            ((int*)mb)[base + 12 + p] = bj[p];
        }
        mb[base + KNN] = 3.4e38f;
        ((int*)mb)[base + 12 + KNN] = 0x7fffffff;
    }
    __syncthreads();

    if (tid < 128) {
        int row = tid;
        int ptr[4] = {0, 0, 0, 0};
        int* outp = idxout + ((long long)(b * NPTS + i0 + row)) * KNN;
#pragma unroll
        for (int q = 0; q < KNN; q++) {
            float bestd = 3.4e38f; int bestj = 0x7fffffff; int bl = 0;
#pragma unroll
            for (int l = 0; l < 4; l++) {
                int base = (row * 4 + l) * 24;
                float dl = mb[base + ptr[l]];
                int jl = ((int*)mb)[base + 12 + ptr[l]];
                if (dl < bestd || (dl == bestd && jl < bestj)) {
                    bestd = dl; bestj = jl; bl = l;
                }
            }
            outp[q] = bestj;
            ptr[bl]++;
        }
    }
}

// ---------------- row squared norms ------------------------------------------------
__global__ void rownorms(const float* __restrict__ feat, int lda, int C,
                         float* __restrict__ nrm)
{
    int g = blockIdx.x * blockDim.x + threadIdx.x;
    const float* p = feat + (long long)g * lda;
    float s = 0.f;
    for (int c = 0; c < C; c += 4) {
        float4 v = *(const float4*)(p + c);
        s += v.x * v.x + v.y * v.y + v.z * v.z + v.w * v.w;
    }
    nrm[g] = s;
}

// ---------------- combine: max_k(yd[j_k]) - yd[i] + yb[i], affine, lrelu ---------
// ycomb: BN x 2O, cols [0,O)=yd, [O,2O)=yb
__global__ void combine2(const float* __restrict__ ycomb,
                         const int* __restrict__ idx, const float* __restrict__ s,
                         const float* __restrict__ t, float* __restrict__ outx, int O)
{
    int g = blockIdx.x * blockDim.x + threadIdx.x;   // bn*O + o
    int bn = g / O;
    int o = g - bn * O;
    const int* ip = idx + (long long)bn * KNN;
    int base = bn & ~2047;
    const int ld = 2 * O;
    float m = -3.4e38f;
#pragma unroll
    for (int k = 0; k < KNN; k++) {
        int j = ip[k];
        m = fmaxf(m, ycomb[(long long)(base + j) * ld + o]);
    }
    float h = (m - ycomb[(long long)bn * ld + o] + ycomb[(long long)bn * ld + O + o])
              * s[o] + t[o];
    outx[(long long)bn * 512 + o] = LRELU(h);
}

// ---------------- input padding helpers -------------------------------------------
__global__ void pad_pts(const float* __restrict__ p, float* __restrict__ pp)
{
    int g = blockIdx.x * blockDim.x + threadIdx.x;
    pp[g * 4 + 0] = p[g * 3 + 0];
    pp[g * 4 + 1] = p[g * 3 + 1];
    pp[g * 4 + 2] = p[g * 3 + 2];
    pp[g * 4 + 3] = 0.f;
}
__global__ void pad_w1(const float* __restrict__ W1, float* __restrict__ wd,
                       float* __restrict__ wb)
{
    int o = threadIdx.x;
#pragma unroll
    for (int c = 0; c < 3; c++) {
        wd[o * 4 + c] = W1[o * 6 + c];
        wb[o * 4 + c] = W1[o * 6 + 3 + c];
    }
    wd[o * 4 + 3] = 0.f;
    wb[o * 4 + 3] = 0.f;
}

// ---------------- global max pool over N + affine + lrelu ------------------------
__global__ void maxpool(const float* __restrict__ H, const float* __restrict__ s5,
                        const float* __restrict__ t5, float* __restrict__ pooled)
{
    int b = blockIdx.y;
    int o = blockIdx.x * blockDim.x + threadIdx.x;
    const float* p = H + (long long)b * NPTS * 1024 + o;
    float m0 = -3.4e38f, m1 = -3.4e38f, m2 = -3.4e38f, m3 = -3.4e38f;
    for (int n = 0; n < NPTS; n += 4) {
        m0 = fmaxf(m0, p[(long long)(n + 0) * 1024]);
        m1 = fmaxf(m1, p[(long long)(n + 1) * 1024]);
        m2 = fmaxf(m2, p[(long long)(n + 2) * 1024]);
        m3 = fmaxf(m3, p[(long long)(n + 3) * 1024]);
    }
    float m = fmaxf(fmaxf(m0, m1), fmaxf(m2, m3));
    float h = m * s5[o] + t5[o];
    pooled[b * 1024 + o] = LRELU(h);
}

// ---------------- final 3 FC layers, fused -----------------------------------------
__global__ void final_fc(const float* __restrict__ pooled,
                         const float* __restrict__ Wf1, const float* __restrict__ sf1,
                         const float* __restrict__ tf1,
                         const float* __restrict__ Wf2, const float* __restrict__ bf2,
                         const float* __restrict__ sf2, const float* __restrict__ tf2,
                         const float* __restrict__ Wf3, const float* __restrict__ bf3,
                         float* __restrict__ out)
{
    __shared__ float sx[1024];
    __shared__ float h1[512];
    __shared__ float h2[256];
    int b = blockIdx.x, tid = threadIdx.x;
    sx[tid] = pooled[b * 1024 + tid];
    sx[tid + 512] = pooled[b * 1024 + tid + 512];
    __syncthreads();
    {
        const float* w = Wf1 + (long long)tid * 1024;
        float a0 = 0.f, a1 = 0.f, a2 = 0.f, a3 = 0.f;
        for (int c = 0; c < 1024; c += 4) {
            a0 = fmaf(w[c + 0], sx[c + 0], a0);
            a1 = fmaf(w[c + 1], sx[c + 1], a1);
            a2 = fmaf(w[c + 2], sx[c + 2], a2);
            a3 = fmaf(w[c + 3], sx[c + 3], a3);
        }
        float h = ((a0 + a1) + (a2 + a3)) * sf1[tid] + tf1[tid];
        h1[tid] = LRELU(h);
    }
    __syncthreads();
    if (tid < 256) {
        const float* w = Wf2 + (long long)tid * 512;
        float a0 = 0.f, a1 = 0.f, a2 = 0.f, a3 = 0.f;
        for (int c = 0; c < 512; c += 4) {
            a0 = fmaf(w[c + 0], h1[c + 0], a0);
            a1 = fmaf(w[c + 1], h1[c + 1], a1);
            a2 = fmaf(w[c + 2], h1[c + 2], a2);
            a3 = fmaf(w[c + 3], h1[c + 3], a3);
        }
        float h = (((a0 + a1) + (a2 + a3)) + bf2[tid]) * sf2[tid] + tf2[tid];
        h2[tid] = LRELU(h);
    }
    __syncthreads();
    if (tid < 3) {
        const float* w = Wf3 + (long long)tid * 256;
        float a = 0.f;
        for (int c = 0; c < 256; c++) a = fmaf(w[c], h2[c], a);
        out[b * 3 + tid] = a + bf3[tid];
    }
}

// ------------------------------- host side ---------------------------------------
extern "C" void kernel_launch(void* const* d_in, const int* in_sizes, int n_in,
                              void* d_out, int out_size)
{
    const float* points = (const float*)d_in[0];
    const float* W1 = (const float*)d_in[1];  const float* s1 = (const float*)d_in[2];  const float* t1 = (const float*)d_in[3];
    const float* W2 = (const float*)d_in[4];  const float* s2 = (const float*)d_in[5];  const float* t2 = (const float*)d_in[6];
    const float* W3 = (const float*)d_in[7];  const float* s3 = (const float*)d_in[8];  const float* t3 = (const float*)d_in[9];
    const float* W4 = (const float*)d_in[10]; const float* s4 = (const float*)d_in[11]; const float* t4 = (const float*)d_in[12];
    const float* W5 = (const float*)d_in[13]; const float* s5 = (const float*)d_in[14]; const float* t5 = (const float*)d_in[15];
    const float* Wf1 = (const float*)d_in[16]; const float* sf1 = (const float*)d_in[17]; const float* tf1 = (const float*)d_in[18];
    const float* Wf2 = (const float*)d_in[19]; const float* bf2 = (const float*)d_in[20];
    const float* sf2 = (const float*)d_in[21]; const float* tf2 = (const float*)d_in[22];
    const float* Wf3 = (const float*)d_in[23]; const float* bf3 = (const float*)d_in[24];

    float *xcat, *nrm, *ycomb, *hh, *pool, *pts, *w1d, *w1b;
    int* idx;
    __nv_bfloat16 *a3, *w3;
    cudaGetSymbolAddress((void**)&xcat,  g_xcat);
    cudaGetSymbolAddress((void**)&nrm,   g_nrm);
    cudaGetSymbolAddress((void**)&idx,   g_idx);
    cudaGetSymbolAddress((void**)&ycomb, g_ycomb);
    cudaGetSymbolAddress((void**)&hh,    g_hh);
    cudaGetSymbolAddress((void**)&pool,  g_pool);
    cudaGetSymbolAddress((void**)&pts,   g_pts);
    cudaGetSymbolAddress((void**)&w1d,   g_w1d);
    cudaGetSymbolAddress((void**)&w1b,   g_w1b);
    cudaGetSymbolAddress((void**)&a3,    g_a3);
    cudaGetSymbolAddress((void**)&w3,    g_w3);

    cudaFuncSetAttribute(gramknn, cudaFuncAttributeMaxDynamicSharedMemorySize,
                         GK_SMEM_BYTES);

    const int BN = BN_TOT;   // 16384

    pad_pts<<<BN / 256, 256>>>(points, pts);
    pad_w1<<<1, 64>>>(W1, w1d, w1b);

    // one edge layer: feat BN x C (stride lda); Wd/Wb O x C (stride ldw)
    auto edge = [&](const float* feat, int lda, int C, int O,
                    const float* Wd, const float* Wb, int ldw,
                    const float* s, const float* t, int coff) {
        rownorms<<<BN / 256, 256>>>(feat, lda, C, nrm);
        gramknn<<<dim3(16, NB), 512, GK_SMEM_BYTES>>>(feat, lda, C, nrm, idx);
        int Kp = ((3 * C + 31) / 32) * 32;
        long long ta = (long long)BN * Kp;
        split3_feat<<<(unsigned)((ta + 255) / 256), 256>>>(feat, lda, C, Kp, a3, ta);
        long long tw = (long long)O * Kp;
        split3_w<<<(unsigned)((tw + 255) / 256), 256>>>(Wd, ldw, C, Kp, w3, 0, tw);
        split3_w<<<(unsigned)((tw + 255) / 256), 256>>>(Wb, ldw, C, Kp, w3, O, tw);
        int N = 2 * O;
        hgemm<<<dim3(BN / 128, N / 128), 256>>>(a3, w3, ycomb, BN, N, Kp, N);
        combine2<<<(BN * O) / 256, 256>>>(ycomb, idx, s, t, xcat + coff, O);
    };

    edge(pts,        4,   4,   64, w1d, w1b,      4,   s1, t1, 0);
    edge(xcat + 0,   512, 64,  64, W2,  W2 + 64,  128, s2, t2, 64);
    edge(xcat + 64,  512, 64,  128, W3, W3 + 64,  128, s3, t3, 128);
    edge(xcat + 128, 512, 128, 256, W4, W4 + 128, 256, s4, t4, 256);

    // point MLP: (16384 x 512) @ (512 x 1024)^T via split-bf16 HMMA
    {
        const int C = 512, O = 1024, Kp = 1536;
        long long ta = (long long)BN * Kp;
        split3_feat<<<(unsigned)((ta + 255) / 256), 256>>>(xcat, 512, C, Kp, a3, ta);
        long long tw = (long long)O * Kp;
        split3_w<<<(unsigned)((tw + 255) / 256), 256>>>(W5, 512, C, Kp, w3, 0, tw);
        hgemm<<<dim3(BN / 128, O / 128), 256>>>(a3, w3, hh, BN, O, Kp, O);
    }
    maxpool<<<dim3(1024 / 256, NB), 256>>>(hh, s5, t5, pool);
    final_fc<<<NB, 512>>>(pool, Wf1, sf1, tf1, Wf2, bf2, sf2, tf2, Wf3, bf3,
                          (float*)d_out);
}